// round 2
// baseline (speedup 1.0000x reference)
#include <cuda_runtime.h>

#define NAG   32
#define DIN   256
#define HID   128
#define NACT  32
#define NEGV  9e15f
#define STR   34   // padded inner stride for transposed [dim][agent] tiles

// ---- shared memory layout (floats) ----
#define OFF_XT   0                    // [256][STR] x transposed; later reused as OT [128][STR]
#define OFF_HT   (256*STR)            // [128][STR] current hidden (transposed)
#define OFF_VT   (OFF_HT + 128*STR)
#define OFF_QT   (OFF_VT + 128*STR)
#define OFF_KT   (OFF_QT + 128*STR)
#define OFF_PT   (OFF_KT + 128*STR)   // probs transposed [j][i], [32][STR]
#define OFF_MK   (OFF_PT + 32*STR)    // mask row-major [i][j], [32][32]
#define SMEM_FLOATS (OFF_MK + NAG*NAG)
#define SMEM_BYTES  (SMEM_FLOATS * 4)

// packed fp32x2 FMA: d = a*b + c elementwise on float2 (Blackwell f32x2 pipe, 2 MACs/issue)
__device__ __forceinline__ float2 ffma2v(float2 a, float2 b, float2 c) {
    union F2U { float2 f; unsigned long long u; };
    F2U A, Bv, C, D;
    A.f = a; Bv.f = b; C.f = c;
    asm("fma.rn.f32x2 %0, %1, %2, %3;"
        : "=l"(D.u) : "l"(A.u), "l"(Bv.u), "l"(C.u));
    return D.f;
}

// dstT[t][i] = act(srcT^T @ W + bias) for this thread's column t and 16 rows (8 row-pairs)
// srcT: [K][STR] transposed activations in smem; W: [K][HID] row-major global.
template <bool RELU>
__device__ __forceinline__ void proj_f32x2(
    const float* __restrict__ srcT, int K,
    const float* __restrict__ W, const float* __restrict__ bias,
    float* __restrict__ dstT, int t, int rbase)
{
    float2 acc[8];
#pragma unroll
    for (int p = 0; p < 8; ++p) acc[p] = make_float2(0.f, 0.f);
#pragma unroll 4
    for (int k = 0; k < K; ++k) {
        float w = W[k * HID + t];
        float2 w2 = make_float2(w, w);
        const float2* xr = reinterpret_cast<const float2*>(srcT + k * STR + rbase);
#pragma unroll
        for (int p = 0; p < 8; ++p) acc[p] = ffma2v(xr[p], w2, acc[p]);
    }
    float bb = bias[t];
    float2 b2 = make_float2(bb, bb);
#pragma unroll
    for (int p = 0; p < 8; ++p) {
        float2 r;
        r.x = acc[p].x + b2.x;
        r.y = acc[p].y + b2.y;
        if (RELU) { r.x = fmaxf(r.x, 0.f); r.y = fmaxf(r.y, 0.f); }
        *reinterpret_cast<float2*>(dstT + t * STR + rbase + 2 * p) = r;
    }
}

__device__ __forceinline__ void att_block(
    float* __restrict__ sm,
    const float* __restrict__ vw, const float* __restrict__ vb,
    const float* __restrict__ kw, const float* __restrict__ kb,
    const float* __restrict__ qw, const float* __restrict__ qb,
    const float* __restrict__ ow, const float* __restrict__ ob,
    int tid)
{
    float* sXT = sm + OFF_XT;   // reused here as attention-output (transposed)
    float* sHT = sm + OFF_HT;
    float* sVT = sm + OFF_VT;
    float* sQT = sm + OFF_QT;
    float* sKT = sm + OFF_KT;
    float* sPT = sm + OFF_PT;
    float* sMK = sm + OFF_MK;

    const int t     = tid & 127;         // output column (feature)
    const int rbase = (tid >> 7) << 4;   // 0 or 16: this thread's 16-row slab

    // ---- V, Q, K projections (fused: reuse each h read for 3 FMAs) ----
    {
        float2 av[8], aq[8], ak[8];
#pragma unroll
        for (int p = 0; p < 8; ++p) {
            av[p] = make_float2(0.f, 0.f);
            aq[p] = make_float2(0.f, 0.f);
            ak[p] = make_float2(0.f, 0.f);
        }
#pragma unroll 2
        for (int k = 0; k < HID; ++k) {
            float wv = vw[k * HID + t];
            float wq = qw[k * HID + t];
            float wk = kw[k * HID + t];
            float2 wv2 = make_float2(wv, wv);
            float2 wq2 = make_float2(wq, wq);
            float2 wk2 = make_float2(wk, wk);
            const float2* xr = reinterpret_cast<const float2*>(sHT + k * STR + rbase);
#pragma unroll
            for (int p = 0; p < 8; ++p) {
                float2 h2 = xr[p];
                av[p] = ffma2v(h2, wv2, av[p]);
                aq[p] = ffma2v(h2, wq2, aq[p]);
                ak[p] = ffma2v(h2, wk2, ak[p]);
            }
        }
        float bv = vb[t], bq = qb[t], bk = kb[t];
#pragma unroll
        for (int p = 0; p < 8; ++p) {
            float2 r;
            r.x = fmaxf(av[p].x + bv, 0.f); r.y = fmaxf(av[p].y + bv, 0.f);
            *reinterpret_cast<float2*>(sVT + t * STR + rbase + 2 * p) = r;
            r.x = fmaxf(aq[p].x + bq, 0.f); r.y = fmaxf(aq[p].y + bq, 0.f);
            *reinterpret_cast<float2*>(sQT + t * STR + rbase + 2 * p) = r;
            r.x = fmaxf(ak[p].x + bk, 0.f); r.y = fmaxf(ak[p].y + bk, 0.f);
            *reinterpret_cast<float2*>(sKT + t * STR + rbase + 2 * p) = r;
        }
    }
    __syncthreads();

    // ---- scores + mask: logits[i][j] = q_i . k_j masked; write transposed sPT[j][i] ----
    {
        const int j  = tid & 31;     // lane: key index
        const int ib = tid >> 5;     // warp: base query row
        float sc0 = 0.f, sc1 = 0.f, sc2 = 0.f, sc3 = 0.f;
#pragma unroll 4
        for (int h = 0; h < HID; ++h) {
            float kv = sKT[h * STR + j];
            sc0 = fmaf(sQT[h * STR + ib],      kv, sc0);
            sc1 = fmaf(sQT[h * STR + ib + 8],  kv, sc1);
            sc2 = fmaf(sQT[h * STR + ib + 16], kv, sc2);
            sc3 = fmaf(sQT[h * STR + ib + 24], kv, sc3);
        }
        float sc[4] = {sc0, sc1, sc2, sc3};
#pragma unroll
        for (int r = 0; r < 4; ++r) {
            int i = ib + 8 * r;
            float m = sMK[i * NAG + j];
            sPT[j * STR + i] = sc[r] * m - NEGV * (1.0f - m);
        }
    }
    __syncthreads();

    // ---- softmax over j for each row i (warp 0; lane = row) ----
    if (tid < NAG) {
        const int i = tid;
        float mx = sPT[0 * STR + i];
#pragma unroll
        for (int j = 1; j < NAG; ++j) mx = fmaxf(mx, sPT[j * STR + i]);
        float s = 0.f;
#pragma unroll
        for (int j = 0; j < NAG; ++j) {
            float e = expf(sPT[j * STR + i] - mx);
            sPT[j * STR + i] = e;
            s += e;
        }
        float inv = 1.0f / s;
#pragma unroll
        for (int j = 0; j < NAG; ++j) sPT[j * STR + i] *= inv;
    }
    __syncthreads();

    // ---- out = P @ V  ->  sXT (transposed) ----
    {
        float2 acc[8];
#pragma unroll
        for (int p = 0; p < 8; ++p) acc[p] = make_float2(0.f, 0.f);
#pragma unroll 2
        for (int j = 0; j < NAG; ++j) {
            float v = sVT[t * STR + j];
            float2 v2 = make_float2(v, v);
            const float2* pr = reinterpret_cast<const float2*>(sPT + j * STR + rbase);
#pragma unroll
            for (int p = 0; p < 8; ++p) acc[p] = ffma2v(pr[p], v2, acc[p]);
        }
#pragma unroll
        for (int p = 0; p < 8; ++p)
            *reinterpret_cast<float2*>(sXT + t * STR + rbase + 2 * p) = acc[p];
    }
    __syncthreads();

    // ---- h' = relu(out @ ow + ob) -> sHT ----
    proj_f32x2<true>(sXT, HID, ow, ob, sHT, t, rbase);
    __syncthreads();
}

__global__ void __launch_bounds__(256, 2)
dgn_kernel(const float* __restrict__ x, const float* __restrict__ mask,
           const float* __restrict__ enc_w, const float* __restrict__ enc_b,
           const float* __restrict__ a1_vw, const float* __restrict__ a1_vb,
           const float* __restrict__ a1_kw, const float* __restrict__ a1_kb,
           const float* __restrict__ a1_qw, const float* __restrict__ a1_qb,
           const float* __restrict__ a1_ow, const float* __restrict__ a1_ob,
           const float* __restrict__ a2_vw, const float* __restrict__ a2_vb,
           const float* __restrict__ a2_kw, const float* __restrict__ a2_kb,
           const float* __restrict__ a2_qw, const float* __restrict__ a2_qb,
           const float* __restrict__ a2_ow, const float* __restrict__ a2_ob,
           const float* __restrict__ qhw, const float* __restrict__ qhb,
           float* __restrict__ out)
{
    extern __shared__ float sm[];
    float* sXT = sm + OFF_XT;
    float* sHT = sm + OFF_HT;
    float* sMK = sm + OFF_MK;

    const int b   = blockIdx.x;
    const int tid = threadIdx.x;
    const int t     = tid & 127;
    const int rbase = (tid >> 7) << 4;

    // ---- load x (transposed into smem) and mask ----
    {
        const float4* xg = reinterpret_cast<const float4*>(x + (size_t)b * NAG * DIN);
#pragma unroll 2
        for (int idx = tid; idx < NAG * DIN / 4; idx += 256) {
            float4 v = xg[idx];
            int lin = idx * 4;
            int i = lin >> 8;       // / DIN
            int d = lin & 255;      // % DIN
            sXT[(d + 0) * STR + i] = v.x;
            sXT[(d + 1) * STR + i] = v.y;
            sXT[(d + 2) * STR + i] = v.z;
            sXT[(d + 3) * STR + i] = v.w;
        }
        const float4* mg = reinterpret_cast<const float4*>(mask + (size_t)b * NAG * NAG);
        reinterpret_cast<float4*>(sMK)[tid] = mg[tid];  // 1024 floats == 256 float4
    }
    __syncthreads();

    // ---- encoder: h1 = relu(x @ enc_w + enc_b) ----
    proj_f32x2<true>(sXT, DIN, enc_w, enc_b, sHT, t, rbase);
    __syncthreads();

    // ---- two attention blocks ----
    att_block(sm, a1_vw, a1_vb, a1_kw, a1_kb, a1_qw, a1_qb, a1_ow, a1_ob, tid);
    att_block(sm, a2_vw, a2_vb, a2_kw, a2_kb, a2_qw, a2_qb, a2_ow, a2_ob, tid);

    // ---- head: q = h3 @ q_w + q_b  [32,32] ----
    {
        const int a  = tid & 31;
        const int ig = tid >> 5;
        float acc[4] = {0.f, 0.f, 0.f, 0.f};
#pragma unroll 4
        for (int d = 0; d < HID; ++d) {
            float w = qhw[d * NACT + a];
            acc[0] = fmaf(sHT[d * STR + ig],      w, acc[0]);
            acc[1] = fmaf(sHT[d * STR + ig + 8],  w, acc[1]);
            acc[2] = fmaf(sHT[d * STR + ig + 16], w, acc[2]);
            acc[3] = fmaf(sHT[d * STR + ig + 24], w, acc[3]);
        }
        float bb = qhb[a];
        float* og = out + (size_t)b * NAG * NACT;
#pragma unroll
        for (int r = 0; r < 4; ++r)
            og[(ig + 8 * r) * NACT + a] = acc[r] + bb;
    }
}

extern "C" void kernel_launch(void* const* d_in, const int* in_sizes, int n_in,
                              void* d_out, int out_size)
{
    const float* x     = (const float*)d_in[0];
    const float* mask  = (const float*)d_in[1];
    const float* enc_w = (const float*)d_in[2];
    const float* enc_b = (const float*)d_in[3];
    const float* a1_vw = (const float*)d_in[4];
    const float* a1_vb = (const float*)d_in[5];
    const float* a1_kw = (const float*)d_in[6];
    const float* a1_kb = (const float*)d_in[7];
    const float* a1_qw = (const float*)d_in[8];
    const float* a1_qb = (const float*)d_in[9];
    const float* a1_ow = (const float*)d_in[10];
    const float* a1_ob = (const float*)d_in[11];
    const float* a2_vw = (const float*)d_in[12];
    const float* a2_vb = (const float*)d_in[13];
    const float* a2_kw = (const float*)d_in[14];
    const float* a2_kb = (const float*)d_in[15];
    const float* a2_qw = (const float*)d_in[16];
    const float* a2_qb = (const float*)d_in[17];
    const float* a2_ow = (const float*)d_in[18];
    const float* a2_ob = (const float*)d_in[19];
    const float* q_w   = (const float*)d_in[20];
    const float* q_b   = (const float*)d_in[21];

    cudaFuncSetAttribute(dgn_kernel, cudaFuncAttributeMaxDynamicSharedMemorySize, SMEM_BYTES);

    dgn_kernel<<<4096, 256, SMEM_BYTES>>>(
        x, mask, enc_w, enc_b,
        a1_vw, a1_vb, a1_kw, a1_kb, a1_qw, a1_qb, a1_ow, a1_ob,
        a2_vw, a2_vb, a2_kw, a2_kb, a2_qw, a2_qb, a2_ow, a2_ob,
        q_w, q_b, (float*)d_out);
}

// round 4
// speedup vs baseline: 2.2048x; 2.2048x over previous
#include <cuda_runtime.h>
#include <cstdint>

#define NAG 32
#define HID 128

// ---- smem layout (bytes): two 128-row weight tiles + three 64-row act tiles ----
#define W0OFF 0
#define W1OFF 65536
#define HOFF  131072
#define SOFF  163840
#define QOFF  196608
#define SM_TOTAL 229376

// swizzled byte offset in a [rows][128] f32 tile (row stride 512B, 16B-chunk XOR)
__device__ __forceinline__ uint32_t SW(int r, int c) {
    return (uint32_t)(r * 512 + ((((c >> 2) ^ (r & 7)) << 4) | ((c & 3) << 2)));
}

__device__ __forceinline__ uint32_t s2u(const void* p) {
    uint32_t a;
    asm("{ .reg .u64 t; cvta.to.shared.u64 t, %1; cvt.u32.u64 %0, t; }" : "=r"(a) : "l"(p));
    return a;
}
__device__ __forceinline__ uint32_t f2tf(float f) {
    uint32_t u;
    asm("cvt.rna.tf32.f32 %0, %1;" : "=r"(u) : "f"(f));
    return u;
}
__device__ __forceinline__ uint32_t lds(uint32_t a) {
    uint32_t v;
    asm volatile("ld.shared.b32 %0, [%1];" : "=r"(v) : "r"(a));
    return v;
}
__device__ __forceinline__ float ldsf(uint32_t a) {
    float v;
    asm volatile("ld.shared.b32 %0, [%1];" : "=f"(v) : "r"(a));
    return v;
}
__device__ __forceinline__ void sts2(uint32_t a, uint32_t x, uint32_t y) {
    asm volatile("st.shared.v2.b32 [%0], {%1,%2};" :: "r"(a), "r"(x), "r"(y));
}
__device__ __forceinline__ void sts4(uint32_t a, uint32_t x, uint32_t y, uint32_t z, uint32_t w) {
    asm volatile("st.shared.v4.b32 [%0], {%1,%2,%3,%4};" :: "r"(a), "r"(x), "r"(y), "r"(z), "r"(w));
}

__device__ __forceinline__ void mma_tf32(float c[4], const uint32_t a[4], const uint32_t b[2]) {
    asm volatile("mma.sync.aligned.m16n8k8.row.col.f32.tf32.tf32.f32 "
        "{%0,%1,%2,%3}, {%4,%5,%6,%7}, {%8,%9}, {%0,%1,%2,%3};"
        : "+f"(c[0]), "+f"(c[1]), "+f"(c[2]), "+f"(c[3])
        : "r"(a[0]), "r"(a[1]), "r"(a[2]), "r"(a[3]), "r"(b[0]), "r"(b[1]));
}

__device__ __forceinline__ void zacc(float a[2][4][4]) {
#pragma unroll
    for (int i = 0; i < 2; ++i)
#pragma unroll
        for (int j = 0; j < 4; ++j)
#pragma unroll
            for (int k = 0; k < 4; ++k) a[i][j][k] = 0.f;
}

// warp GEMM: C[64 x 8*NFRAG*4warps] += A[64xK] * B, K = 8*KSTEPS.
// A: smem tile [m][k]. B normal: smem tile [n][k]. B trans: smem tile [k][n].
template<int NFRAG, int KSTEPS, bool BTR>
__device__ __forceinline__ void wgemm(float acc[2][4][4], uint32_t At, uint32_t Bt,
                                      int w, int lane) {
    const int gid = lane >> 2, ctig = lane & 3;
    const int ar0 = (w & 1) * 32 + gid;
    const int nb = (w >> 1) * (8 * NFRAG);
#pragma unroll
    for (int s = 0; s < KSTEPS; ++s) {
        const int k0 = 8 * s;
        uint32_t a[2][4];
#pragma unroll
        for (int mi = 0; mi < 2; ++mi) {
            int r = ar0 + 16 * mi;
            a[mi][0] = lds(At + SW(r,     k0 + ctig));
            a[mi][1] = lds(At + SW(r + 8, k0 + ctig));
            a[mi][2] = lds(At + SW(r,     k0 + ctig + 4));
            a[mi][3] = lds(At + SW(r + 8, k0 + ctig + 4));
        }
        uint32_t b[NFRAG][2];
#pragma unroll
        for (int nf = 0; nf < NFRAG; ++nf) {
            int n = nb + 8 * nf + gid;
            if (BTR) {
                b[nf][0] = lds(Bt + SW(k0 + ctig,     n));
                b[nf][1] = lds(Bt + SW(k0 + ctig + 4, n));
            } else {
                b[nf][0] = lds(Bt + SW(n, k0 + ctig));
                b[nf][1] = lds(Bt + SW(n, k0 + ctig + 4));
            }
        }
#pragma unroll
        for (int mi = 0; mi < 2; ++mi)
#pragma unroll
            for (int nf = 0; nf < NFRAG; ++nf)
                mma_tf32(acc[mi][nf], a[mi], b[nf]);
    }
}

// ---- weight loaders: gmem [128][128] row-major -> smem tile [n][k] (transposed) ----
__device__ __forceinline__ void wldg(const float* W, int w, int lane, float4* rg) {
    const int n = 32 * (w & 3) + lane, k0 = (w >> 2) * 64;
    const float* p = W + n;
#pragma unroll
    for (int i = 0; i < 16; ++i) {
        int k = k0 + 4 * i;
        rg[i].x = __ldg(p + (size_t)(k + 0) * HID);
        rg[i].y = __ldg(p + (size_t)(k + 1) * HID);
        rg[i].z = __ldg(p + (size_t)(k + 2) * HID);
        rg[i].w = __ldg(p + (size_t)(k + 3) * HID);
    }
}
__device__ __forceinline__ void wsts(uint32_t dst, int w, int lane, const float4* rg) {
    const int n = 32 * (w & 3) + lane, k0 = (w >> 2) * 64;
#pragma unroll
    for (int i = 0; i < 16; ++i)
        sts4(dst + SW(n, k0 + 4 * i),
             f2tf(rg[i].x), f2tf(rg[i].y), f2tf(rg[i].z), f2tf(rg[i].w));
}
// head weight [128][32] -> smem tile [n=32][k=128]
__device__ __forceinline__ void wldg_head(const float* W, int w, int lane, float4* rg) {
    const int k0 = 16 * w;
#pragma unroll
    for (int i = 0; i < 4; ++i) {
        int k = k0 + 4 * i;
        rg[i].x = __ldg(W + (size_t)(k + 0) * 32 + lane);
        rg[i].y = __ldg(W + (size_t)(k + 1) * 32 + lane);
        rg[i].z = __ldg(W + (size_t)(k + 2) * 32 + lane);
        rg[i].w = __ldg(W + (size_t)(k + 3) * 32 + lane);
    }
}
__device__ __forceinline__ void wsts_head(uint32_t dst, int w, int lane, const float4* rg) {
    const int k0 = 16 * w;
#pragma unroll
    for (int i = 0; i < 4; ++i)
        sts4(dst + SW(lane, k0 + 4 * i),
             f2tf(rg[i].x), f2tf(rg[i].y), f2tf(rg[i].z), f2tf(rg[i].w));
}

// ---- epilogue: acc -> smem tile (bias+relu optional; RAW keeps fp32, else tf32) ----
template<int NFRAG, bool RAW>
__device__ __forceinline__ void epi(uint32_t dst, float acc[2][4][4], const float* bias,
                                    bool relu, int w, int lane) {
    const int r0 = (w & 1) * 32 + (lane >> 2);
    const int nc0 = (w >> 1) * (8 * NFRAG);
#pragma unroll
    for (int mi = 0; mi < 2; ++mi)
#pragma unroll
        for (int nf = 0; nf < NFRAG; ++nf) {
            int col = nc0 + 8 * nf + 2 * (lane & 3);
            float bb0 = bias ? __ldg(bias + col)     : 0.f;
            float bb1 = bias ? __ldg(bias + col + 1) : 0.f;
#pragma unroll
            for (int hh = 0; hh < 2; ++hh) {
                int r = r0 + 16 * mi + 8 * hh;
                float v0 = acc[mi][nf][2 * hh + 0] + bb0;
                float v1 = acc[mi][nf][2 * hh + 1] + bb1;
                if (relu) { v0 = fmaxf(v0, 0.f); v1 = fmaxf(v1, 0.f); }
                uint32_t u0 = RAW ? __float_as_uint(v0) : f2tf(v0);
                uint32_t u1 = RAW ? __float_as_uint(v1) : f2tf(v1);
                sts2(dst + SW(r, col), u0, u1);
            }
        }
}

// softmax on 64 rows of t1 (logits raw fp32 in cols 0..63); P (tf32) written back,
// off-diagonal blocks zeroed. Executed by warps 0,1; lane = row within 32-row group.
__device__ __forceinline__ void softmax2(uint32_t t1, const float* mask, int b0,
                                         int w, int lane) {
    const int i = 32 * w + lane, g = w;
    const float* mrow = mask + ((size_t)(b0 + g) * NAG + lane) * NAG;
    float l[32];
    float mx = -3.4e38f;
#pragma unroll
    for (int j = 0; j < 32; ++j) {
        float s = ldsf(t1 + SW(i, 32 * g + j));
        float m = __ldg(mrow + j);
        float v = s * m - 9e15f * (1.0f - m);
        l[j] = v;
        mx = fmaxf(mx, v);
    }
    float sum = 0.f;
#pragma unroll
    for (int j = 0; j < 32; ++j) { float e = __expf(l[j] - mx); l[j] = e; sum += e; }
    float inv = 1.0f / sum;
#pragma unroll
    for (int j = 0; j < 32; j += 2) {
        sts2(t1 + SW(i, 32 * g + j), f2tf(l[j] * inv), f2tf(l[j + 1] * inv));
        sts2(t1 + SW(i, 32 * (1 - g) + j), 0u, 0u);
    }
}

// one attention block; kw already resident in Wa; loads nextw into Wa for the next stage
template<bool LAST>
__device__ __forceinline__ void att_block(
    uint32_t h, uint32_t t1, uint32_t t2, uint32_t Wa, uint32_t Wb,
    const float* kb, const float* qw, const float* qb,
    const float* vw, const float* vb, const float* ow, const float* ob,
    const float* nextw, const float* mask, int b0, int w, int lane,
    float acc[2][4][4])
{
    float4 rg[16];
    // K proj
    zacc(acc); wgemm<4, 16, false>(acc, h, Wa, w, lane);
    __syncthreads();
    wldg(qw, w, lane, rg);
    epi<4, false>(t1, acc, kb, true, w, lane);
    wsts(Wb, w, lane, rg);
    __syncthreads();
    // Q proj
    zacc(acc); wgemm<4, 16, false>(acc, h, Wb, w, lane);
    __syncthreads();
    wldg(vw, w, lane, rg);
    epi<4, false>(t2, acc, qb, true, w, lane);
    wsts(Wa, w, lane, rg);
    __syncthreads();
    // scores = Q @ K^T (64x64), raw fp32 logits -> t1
    zacc(acc); wgemm<2, 16, false>(acc, t2, t1, w, lane);
    __syncthreads();
    wldg(ow, w, lane, rg);
    epi<2, true>(t1, acc, nullptr, false, w, lane);
    wsts(Wb, w, lane, rg);
    __syncthreads();
    // softmax -> P (tf32, block-diagonal) in t1
    if (w < 2) softmax2(t1, mask, b0, w, lane);
    __syncthreads();
    // V proj
    zacc(acc); wgemm<4, 16, false>(acc, h, Wa, w, lane);
    __syncthreads();
    if (LAST) wldg_head(nextw, w, lane, rg); else wldg(nextw, w, lane, rg);
    epi<4, false>(t2, acc, vb, true, w, lane);
    if (LAST) wsts_head(Wa, w, lane, rg); else wsts(Wa, w, lane, rg);
    __syncthreads();
    // PV: A = P [64x64], B = V (stored [j][h], read transposed)
    zacc(acc); wgemm<4, 8, true>(acc, t1, t2, w, lane);
    __syncthreads();
    epi<4, false>(h, acc, nullptr, false, w, lane);
    __syncthreads();
    // out proj
    zacc(acc); wgemm<4, 16, false>(acc, h, Wb, w, lane);
    __syncthreads();
    epi<4, false>(t1, acc, ob, true, w, lane);
    __syncthreads();
}

__global__ void __launch_bounds__(256, 1)
dgn_mma(const float* __restrict__ x, const float* __restrict__ mask,
        const float* __restrict__ enc_w, const float* __restrict__ enc_b,
        const float* __restrict__ a1_vw, const float* __restrict__ a1_vb,
        const float* __restrict__ a1_kw, const float* __restrict__ a1_kb,
        const float* __restrict__ a1_qw, const float* __restrict__ a1_qb,
        const float* __restrict__ a1_ow, const float* __restrict__ a1_ob,
        const float* __restrict__ a2_vw, const float* __restrict__ a2_vb,
        const float* __restrict__ a2_kw, const float* __restrict__ a2_kb,
        const float* __restrict__ a2_qw, const float* __restrict__ a2_qb,
        const float* __restrict__ a2_ow, const float* __restrict__ a2_ob,
        const float* __restrict__ qhw, const float* __restrict__ qhb,
        float* __restrict__ out)
{
    extern __shared__ __align__(16) char sm[];
    const uint32_t base = s2u(sm);
    const uint32_t W0v = base + W0OFF, W1v = base + W1OFF;
    const uint32_t Hb = base + HOFF, Sb = base + SOFF, Qb = base + QOFF;
    const int tid = threadIdx.x, w = tid >> 5, lane = tid & 31;
    const int b0 = blockIdx.x * 2;

    float acc[2][4][4];
    float4 rg[16];

    // ---- load x (tf32) into Hb (cols 0..127) and Sb (cols 128..255); enc weights ----
#pragma unroll
    for (int it = 0; it < 16; ++it) {
        int idx = tid + 256 * it;          // 0..4095
        int r = idx >> 6, ch = idx & 63;
        int col = 4 * ch;
        float4 v = *reinterpret_cast<const float4*>(
            x + (((size_t)b0 + (r >> 5)) * NAG + (r & 31)) * 256 + col);
        uint32_t dst = (col < 128 ? Hb : Sb) + SW(r, col & 127);
        sts4(dst, f2tf(v.x), f2tf(v.y), f2tf(v.z), f2tf(v.w));
    }
    wldg(enc_w, w, lane, rg);             wsts(W0v, w, lane, rg);
    wldg(enc_w + 128 * HID, w, lane, rg); wsts(W1v, w, lane, rg);
    __syncthreads();

    // ---- encoder: h1 = relu(x @ enc_w + enc_b), K=256 in two accumulating passes ----
    zacc(acc);
    wgemm<4, 16, false>(acc, Hb, W0v, w, lane);
    wgemm<4, 16, false>(acc, Sb, W1v, w, lane);
    __syncthreads();
    wldg(a1_kw, w, lane, rg);
    epi<4, false>(Qb, acc, enc_b, true, w, lane);
    wsts(W0v, w, lane, rg);
    __syncthreads();

    // ---- attention blocks ----
    att_block<false>(Qb, Hb, Sb, W0v, W1v,
                     a1_kb, a1_qw, a1_qb, a1_vw, a1_vb, a1_ow, a1_ob,
                     a2_kw, mask, b0, w, lane, acc);
    // h2 now in Hb; a2_kw in W0v
    att_block<true>(Hb, Qb, Sb, W0v, W1v,
                    a2_kb, a2_qw, a2_qb, a2_vw, a2_vb, a2_ow, a2_ob,
                    qhw, mask, b0, w, lane, acc);
    // h3 now in Qb; qhw in W0v

    // ---- head: q = h3 @ q_w + q_b  (N=32) ----
    zacc(acc);
    wgemm<1, 16, false>(acc, Qb, W0v, w, lane);
    {
        const int r0 = (w & 1) * 32 + (lane >> 2);
        const int col = (w >> 1) * 8 + 2 * (lane & 3);
        float bb0 = __ldg(qhb + col), bb1 = __ldg(qhb + col + 1);
#pragma unroll
        for (int mi = 0; mi < 2; ++mi)
#pragma unroll
            for (int hh = 0; hh < 2; ++hh) {
                int r = r0 + 16 * mi + 8 * hh;
                float2 v = make_float2(acc[mi][0][2 * hh] + bb0,
                                       acc[mi][0][2 * hh + 1] + bb1);
                *reinterpret_cast<float2*>(
                    out + (((size_t)b0 + (r >> 5)) * NAG + (r & 31)) * 32 + col) = v;
            }
    }
}

extern "C" void kernel_launch(void* const* d_in, const int* in_sizes, int n_in,
                              void* d_out, int out_size)
{
    cudaFuncSetAttribute(dgn_mma, cudaFuncAttributeMaxDynamicSharedMemorySize, SM_TOTAL);
    dgn_mma<<<2048, 256, SM_TOTAL>>>(
        (const float*)d_in[0],  (const float*)d_in[1],  (const float*)d_in[2],  (const float*)d_in[3],
        (const float*)d_in[4],  (const float*)d_in[5],  (const float*)d_in[6],  (const float*)d_in[7],
        (const float*)d_in[8],  (const float*)d_in[9],  (const float*)d_in[10], (const float*)d_in[11],
        (const float*)d_in[12], (const float*)d_in[13], (const float*)d_in[14], (const float*)d_in[15],
        (const float*)d_in[16], (const float*)d_in[17], (const float*)d_in[18], (const float*)d_in[19],
        (const float*)d_in[20], (const float*)d_in[21], (float*)d_out);
}

// round 5
// speedup vs baseline: 2.3956x; 1.0865x over previous
#include <cuda_runtime.h>
#include <cstdint>

#define NAG 32
#define HID 128

// smem: W0, W1 = 64KB weight tiles ([k][n], chunk-XOR swizzle);
//       H, T1, T2 = 32KB activation tiles ([m][k], SW swizzle)
#define W0OFF 0
#define W1OFF 65536
#define HOFF  131072
#define T1OFF 163840
#define T2OFF 196608
#define SM_TOTAL 229376

// activation tile swizzle: [row][col<128] f32, row stride 512B
__device__ __forceinline__ uint32_t SW(int r, int c) {
    return (uint32_t)(r * 512 + ((((c >> 2) ^ (r & 7)) << 4) | ((c & 3) << 2)));
}

__device__ __forceinline__ uint32_t s2u(const void* p) {
    uint32_t a;
    asm("{ .reg .u64 t; cvta.to.shared.u64 t, %1; cvt.u32.u64 %0, t; }" : "=r"(a) : "l"(p));
    return a;
}
__device__ __forceinline__ uint32_t f2tf(float f) {
    uint32_t u;
    asm("cvt.rna.tf32.f32 %0, %1;" : "=r"(u) : "f"(f));
    return u;
}
__device__ __forceinline__ uint32_t lds(uint32_t a) {
    uint32_t v;
    asm volatile("ld.shared.b32 %0, [%1];" : "=r"(v) : "r"(a));
    return v;
}
__device__ __forceinline__ float ldsf(uint32_t a) {
    float v;
    asm volatile("ld.shared.b32 %0, [%1];" : "=f"(v) : "r"(a));
    return v;
}
__device__ __forceinline__ void sts2(uint32_t a, uint32_t x, uint32_t y) {
    asm volatile("st.shared.v2.b32 [%0], {%1,%2};" :: "r"(a), "r"(x), "r"(y));
}
__device__ __forceinline__ void sts4(uint32_t a, uint32_t x, uint32_t y, uint32_t z, uint32_t w) {
    asm volatile("st.shared.v4.b32 [%0], {%1,%2,%3,%4};" :: "r"(a), "r"(x), "r"(y), "r"(z), "r"(w));
}

__device__ __forceinline__ void mma_tf32(float c[4], const uint32_t a[4], const uint32_t b[2]) {
    asm volatile("mma.sync.aligned.m16n8k8.row.col.f32.tf32.tf32.f32 "
        "{%0,%1,%2,%3}, {%4,%5,%6,%7}, {%8,%9}, {%0,%1,%2,%3};"
        : "+f"(c[0]), "+f"(c[1]), "+f"(c[2]), "+f"(c[3])
        : "r"(a[0]), "r"(a[1]), "r"(a[2]), "r"(a[3]), "r"(b[0]), "r"(b[1]));
}

template<int NFRAG>
__device__ __forceinline__ void zacc(float a[2][NFRAG][4]) {
#pragma unroll
    for (int i = 0; i < 2; ++i)
#pragma unroll
        for (int j = 0; j < NFRAG; ++j)
#pragma unroll
            for (int k = 0; k < 4; ++k) a[i][j][k] = 0.f;
}

// A fragment (m16k8) from activation tile
__device__ __forceinline__ void ldA(uint32_t a[4], uint32_t At, int r, int k0, int ctig) {
    a[0] = lds(At + SW(r,     k0 + ctig));
    a[1] = lds(At + SW(r + 8, k0 + ctig));
    a[2] = lds(At + SW(r,     k0 + ctig + 4));
    a[3] = lds(At + SW(r + 8, k0 + ctig + 4));
}

// per-thread constant byte offsets into a weight tile for B fragments
template<int NFRAG>
__device__ __forceinline__ void mk_bofs(uint32_t bofs[NFRAG], int nb, int gid, int ctig) {
#pragma unroll
    for (int nf = 0; nf < NFRAG; ++nf) {
        int n = nb + 8 * nf + gid;
        uint32_t ch = (uint32_t)(n >> 2) ^ ((uint32_t)ctig << 1);   // XOR touches low 3 bits
        bofs[nf] = ch * 16u + (uint32_t)(n & 3) * 4u;
    }
}

// ---- single GEMM, B = weight tile [k][n] ----
template<int NFRAG, int KSTEPS>
__device__ __forceinline__ void wgemm_w(float acc[2][NFRAG][4], uint32_t At, uint32_t Bt,
                                        int w, int lane) {
    const int gid = lane >> 2, ctig = lane & 3;
    const int ar0 = (w & 1) * 32 + gid;
    const int nb = (w >> 1) * (8 * NFRAG);
    uint32_t bofs[NFRAG];
    mk_bofs<NFRAG>(bofs, nb, gid, ctig);
    const uint32_t kbase = Bt + (uint32_t)ctig * 512u;
#pragma unroll
    for (int s = 0; s < KSTEPS; ++s) {
        const int k0 = 8 * s;
        uint32_t a[2][4];
        ldA(a[0], At, ar0,      k0, ctig);
        ldA(a[1], At, ar0 + 16, k0, ctig);
        uint32_t b[NFRAG][2];
#pragma unroll
        for (int nf = 0; nf < NFRAG; ++nf) {
            b[nf][0] = lds(kbase + (uint32_t)k0 * 512u + bofs[nf]);
            b[nf][1] = lds(kbase + (uint32_t)(k0 + 4) * 512u + bofs[nf]);
        }
#pragma unroll
        for (int mi = 0; mi < 2; ++mi)
#pragma unroll
            for (int nf = 0; nf < NFRAG; ++nf)
                mma_tf32(acc[mi][nf], a[mi], b[nf]);
    }
}

// ---- fused dual GEMM: shared A, two weight-B streams (K and Q projections) ----
__device__ __forceinline__ void wgemm_kq(float aK[2][4][4], float aQ[2][4][4],
                                         uint32_t At, uint32_t B0, uint32_t B1,
                                         int w, int lane) {
    const int gid = lane >> 2, ctig = lane & 3;
    const int ar0 = (w & 1) * 32 + gid;
    const int nb = (w >> 1) * 32;
    uint32_t bofs[4];
    mk_bofs<4>(bofs, nb, gid, ctig);
    const uint32_t k0b = B0 + (uint32_t)ctig * 512u;
    const uint32_t k1b = B1 + (uint32_t)ctig * 512u;
#pragma unroll
    for (int s = 0; s < 16; ++s) {
        const int k0 = 8 * s;
        uint32_t a[2][4];
        ldA(a[0], At, ar0,      k0, ctig);
        ldA(a[1], At, ar0 + 16, k0, ctig);
        uint32_t bk[4][2], bq[4][2];
#pragma unroll
        for (int nf = 0; nf < 4; ++nf) {
            bk[nf][0] = lds(k0b + (uint32_t)k0 * 512u + bofs[nf]);
            bk[nf][1] = lds(k0b + (uint32_t)(k0 + 4) * 512u + bofs[nf]);
            bq[nf][0] = lds(k1b + (uint32_t)k0 * 512u + bofs[nf]);
            bq[nf][1] = lds(k1b + (uint32_t)(k0 + 4) * 512u + bofs[nf]);
        }
#pragma unroll
        for (int mi = 0; mi < 2; ++mi)
#pragma unroll
            for (int nf = 0; nf < 4; ++nf) {
                mma_tf32(aK[mi][nf], a[mi], bk[nf]);
                mma_tf32(aQ[mi][nf], a[mi], bq[nf]);
            }
    }
}

// ---- fused: V projection (A=h, B=weight) + scores (A=Q tile, B=K act tile [n][k]) ----
__device__ __forceinline__ void wgemm_vs(float aV[2][4][4], float aS[2][2][4],
                                         uint32_t Ah, uint32_t Wv, uint32_t Aq, uint32_t Bk,
                                         int w, int lane) {
    const int gid = lane >> 2, ctig = lane & 3;
    const int ar0 = (w & 1) * 32 + gid;
    const int nbV = (w >> 1) * 32;
    const int nbS = (w >> 1) * 16;
    uint32_t bofs[4];
    mk_bofs<4>(bofs, nbV, gid, ctig);
    const uint32_t kvb = Wv + (uint32_t)ctig * 512u;
#pragma unroll
    for (int s = 0; s < 16; ++s) {
        const int k0 = 8 * s;
        uint32_t a1[2][4], a2[2][4];
        ldA(a1[0], Ah, ar0,      k0, ctig);
        ldA(a1[1], Ah, ar0 + 16, k0, ctig);
        ldA(a2[0], Aq, ar0,      k0, ctig);
        ldA(a2[1], Aq, ar0 + 16, k0, ctig);
        uint32_t bv[4][2], bs[2][2];
#pragma unroll
        for (int nf = 0; nf < 4; ++nf) {
            bv[nf][0] = lds(kvb + (uint32_t)k0 * 512u + bofs[nf]);
            bv[nf][1] = lds(kvb + (uint32_t)(k0 + 4) * 512u + bofs[nf]);
        }
#pragma unroll
        for (int nf = 0; nf < 2; ++nf) {
            int n = nbS + 8 * nf + gid;
            bs[nf][0] = lds(Bk + SW(n, k0 + ctig));
            bs[nf][1] = lds(Bk + SW(n, k0 + ctig + 4));
        }
#pragma unroll
        for (int mi = 0; mi < 2; ++mi) {
#pragma unroll
            for (int nf = 0; nf < 4; ++nf) mma_tf32(aV[mi][nf], a1[mi], bv[nf]);
#pragma unroll
            for (int nf = 0; nf < 2; ++nf) mma_tf32(aS[mi][nf], a2[mi], bs[nf]);
        }
    }
}

// ---- PV: A = P tile, B = V act tile read transposed ([k][n] indexing), K=64 ----
__device__ __forceinline__ void wgemm_pv(float acc[2][4][4], uint32_t Ap, uint32_t Bv,
                                         int w, int lane) {
    const int gid = lane >> 2, ctig = lane & 3;
    const int ar0 = (w & 1) * 32 + gid;
    const int nb = (w >> 1) * 32;
#pragma unroll
    for (int s = 0; s < 8; ++s) {
        const int k0 = 8 * s;
        uint32_t a[2][4];
        ldA(a[0], Ap, ar0,      k0, ctig);
        ldA(a[1], Ap, ar0 + 16, k0, ctig);
        uint32_t b[4][2];
#pragma unroll
        for (int nf = 0; nf < 4; ++nf) {
            int n = nb + 8 * nf + gid;
            b[nf][0] = lds(Bv + SW(k0 + ctig,     n));
            b[nf][1] = lds(Bv + SW(k0 + ctig + 4, n));
        }
#pragma unroll
        for (int mi = 0; mi < 2; ++mi)
#pragma unroll
            for (int nf = 0; nf < 4; ++nf)
                mma_tf32(acc[mi][nf], a[mi], b[nf]);
    }
}

// ---- weight loader: gmem [128][128] row-major -> smem [k][n] XOR layout, coalesced ----
__device__ __forceinline__ void wload(uint32_t dst, const float* Wg, int w, int lane) {
#pragma unroll
    for (int i0 = 0; i0 < 16; i0 += 8) {
        float4 v[8];
#pragma unroll
        for (int i = 0; i < 8; ++i) {
            int k = 16 * w + i0 + i;
            v[i] = __ldg(reinterpret_cast<const float4*>(Wg + (size_t)k * HID) + lane);
        }
#pragma unroll
        for (int i = 0; i < 8; ++i) {
            int k = 16 * w + i0 + i;
            uint32_t ch = (uint32_t)lane ^ (((uint32_t)k & 3u) << 1);
            sts4(dst + (uint32_t)k * 512u + ch * 16u,
                 f2tf(v[i].x), f2tf(v[i].y), f2tf(v[i].z), f2tf(v[i].w));
        }
    }
}
// head weight [128][32] -> same layout (chunks 0..7 used)
__device__ __forceinline__ void wload_head(uint32_t dst, const float* Wg, int w, int lane) {
#pragma unroll
    for (int i = 0; i < 4; ++i) {
        int k = 16 * w + 4 * i + (lane >> 3);
        int c = lane & 7;
        float4 v = __ldg(reinterpret_cast<const float4*>(Wg + (size_t)k * 32) + c);
        uint32_t ch = (uint32_t)c ^ (((uint32_t)k & 3u) << 1);
        sts4(dst + (uint32_t)k * 512u + ch * 16u,
             f2tf(v.x), f2tf(v.y), f2tf(v.z), f2tf(v.w));
    }
}

// ---- epilogue: acc -> act tile (RAW keeps fp32 bits, else tf32-converted) ----
template<int NFRAG, bool RAW>
__device__ __forceinline__ void epi(uint32_t dst, float acc[2][NFRAG][4], const float* bias,
                                    bool relu, int w, int lane) {
    const int r0 = (w & 1) * 32 + (lane >> 2);
    const int nc0 = (w >> 1) * (8 * NFRAG);
#pragma unroll
    for (int mi = 0; mi < 2; ++mi)
#pragma unroll
        for (int nf = 0; nf < NFRAG; ++nf) {
            int col = nc0 + 8 * nf + 2 * (lane & 3);
            float bb0 = bias ? __ldg(bias + col)     : 0.f;
            float bb1 = bias ? __ldg(bias + col + 1) : 0.f;
#pragma unroll
            for (int hh = 0; hh < 2; ++hh) {
                int r = r0 + 16 * mi + 8 * hh;
                float v0 = acc[mi][nf][2 * hh + 0] + bb0;
                float v1 = acc[mi][nf][2 * hh + 1] + bb1;
                if (relu) { v0 = fmaxf(v0, 0.f); v1 = fmaxf(v1, 0.f); }
                uint32_t u0 = RAW ? __float_as_uint(v0) : f2tf(v0);
                uint32_t u1 = RAW ? __float_as_uint(v1) : f2tf(v1);
                sts2(dst + SW(r, col), u0, u1);
            }
        }
}

// softmax over the two 32x32 diagonal blocks; P (tf32) written, off-diag zeroed
__device__ __forceinline__ void softmax2(uint32_t t1, const float* mask, int b0,
                                         int w, int lane) {
    const int i = 32 * w + lane, g = w;
    const float* mrow = mask + ((size_t)(b0 + g) * NAG + lane) * NAG;
    float l[32];
    float mx = -3.4e38f;
#pragma unroll
    for (int j = 0; j < 32; ++j) {
        float s = ldsf(t1 + SW(i, 32 * g + j));
        float m = __ldg(mrow + j);
        float v = s * m - 9e15f * (1.0f - m);
        l[j] = v;
        mx = fmaxf(mx, v);
    }
    float sum = 0.f;
#pragma unroll
    for (int j = 0; j < 32; ++j) { float e = __expf(l[j] - mx); l[j] = e; sum += e; }
    float inv = 1.0f / sum;
#pragma unroll
    for (int j = 0; j < 32; j += 2) {
        sts2(t1 + SW(i, 32 * g + j), f2tf(l[j] * inv), f2tf(l[j + 1] * inv));
        sts2(t1 + SW(i, 32 * (1 - g) + j), 0u, 0u);
    }
}

// one attention block; kw in W0, qw in W1 on entry; prefetches nw1->W0, nw2->W1
template<bool LAST>
__device__ __forceinline__ void att_block(
    uint32_t H, uint32_t T1, uint32_t T2, uint32_t W0, uint32_t W1,
    const float* kb, const float* qb, const float* vw, const float* vb,
    const float* ow, const float* ob, const float* nw1, const float* nw2,
    const float* mask, int b0, int w, int lane)
{
    {
        float aK[2][4][4], aQ[2][4][4];
        zacc<4>(aK); zacc<4>(aQ);
        wgemm_kq(aK, aQ, H, W0, W1, w, lane);
        __syncthreads();
        wload(W0, vw, w, lane);
        wload(W1, ow, w, lane);
        epi<4, false>(T1, aK, kb, true, w, lane);   // K -> T1 ([j][h])
        epi<4, false>(T2, aQ, qb, true, w, lane);   // Q -> T2 ([i][h])
        __syncthreads();
    }
    {
        float aV[2][4][4]; float aS[2][2][4];
        zacc<4>(aV); zacc<2>(aS);
        wgemm_vs(aV, aS, H, W0, T2, T1, w, lane);
        __syncthreads();
        if (LAST) wload_head(W0, nw1, w, lane); else wload(W0, nw1, w, lane);
        epi<4, false>(H, aV, vb, true, w, lane);    // V -> H ([j][h])
        epi<2, true>(T1, aS, nullptr, false, w, lane); // raw logits -> T1
        __syncthreads();
    }
    if (w < 2) softmax2(T1, mask, b0, w, lane);     // P -> T1 ([i][j], tf32)
    __syncthreads();
    {
        float aP[2][4][4]; zacc<4>(aP);
        wgemm_pv(aP, T1, H, w, lane);               // PV -> acc
        __syncthreads();
        epi<4, false>(T2, aP, nullptr, false, w, lane); // PV -> T2
        __syncthreads();
    }
    {
        float aO[2][4][4]; zacc<4>(aO);
        wgemm_w<4, 16>(aO, T2, W1, w, lane);        // out-proj
        __syncthreads();
        if (!LAST) wload(W1, nw2, w, lane);
        epi<4, false>(H, aO, ob, true, w, lane);    // h' -> H
        __syncthreads();
    }
}

__global__ void __launch_bounds__(256, 1)
dgn_mma(const float* __restrict__ x, const float* __restrict__ mask,
        const float* __restrict__ enc_w, const float* __restrict__ enc_b,
        const float* __restrict__ a1_vw, const float* __restrict__ a1_vb,
        const float* __restrict__ a1_kw, const float* __restrict__ a1_kb,
        const float* __restrict__ a1_qw, const float* __restrict__ a1_qb,
        const float* __restrict__ a1_ow, const float* __restrict__ a1_ob,
        const float* __restrict__ a2_vw, const float* __restrict__ a2_vb,
        const float* __restrict__ a2_kw, const float* __restrict__ a2_kb,
        const float* __restrict__ a2_qw, const float* __restrict__ a2_qb,
        const float* __restrict__ a2_ow, const float* __restrict__ a2_ob,
        const float* __restrict__ qhw, const float* __restrict__ qhb,
        float* __restrict__ out)
{
    extern __shared__ __align__(16) char sm[];
    const uint32_t base = s2u(sm);
    const uint32_t W0v = base + W0OFF, W1v = base + W1OFF;
    const uint32_t Hv = base + HOFF, T1v = base + T1OFF, T2v = base + T2OFF;
    const int tid = threadIdx.x, w = tid >> 5, lane = tid & 31;
    const int b0 = blockIdx.x * 2;

    // ---- load x (tf32) into T1 (cols 0..127) / T2 (cols 128..255); enc weights ----
#pragma unroll
    for (int it = 0; it < 16; ++it) {
        int idx = tid + 256 * it;
        int r = idx >> 6, ch = idx & 63;
        int col = 4 * ch;
        float4 v = *reinterpret_cast<const float4*>(
            x + (((size_t)b0 + (r >> 5)) * NAG + (r & 31)) * 256 + col);
        uint32_t dst = (col < 128 ? T1v : T2v) + SW(r, col & 127);
        sts4(dst, f2tf(v.x), f2tf(v.y), f2tf(v.z), f2tf(v.w));
    }
    wload(W0v, enc_w, w, lane);
    wload(W1v, enc_w + 128 * HID, w, lane);
    __syncthreads();

    // ---- encoder: h1 = relu(x @ enc_w + enc_b), K=256 ----
    {
        float aE[2][4][4]; zacc<4>(aE);
        wgemm_w<4, 16>(aE, T1v, W0v, w, lane);
        wgemm_w<4, 16>(aE, T2v, W1v, w, lane);
        __syncthreads();
        wload(W0v, a1_kw, w, lane);
        wload(W1v, a1_qw, w, lane);
        epi<4, false>(Hv, aE, enc_b, true, w, lane);
        __syncthreads();
    }

    att_block<false>(Hv, T1v, T2v, W0v, W1v,
                     a1_kb, a1_qb, a1_vw, a1_vb, a1_ow, a1_ob,
                     a2_kw, a2_qw, mask, b0, w, lane);
    att_block<true>(Hv, T1v, T2v, W0v, W1v,
                    a2_kb, a2_qb, a2_vw, a2_vb, a2_ow, a2_ob,
                    qhw, nullptr, mask, b0, w, lane);

    // ---- head: q = h3 @ q_w + q_b (N=32), direct to gmem ----
    {
        float aH[2][1][4]; zacc<1>(aH);
        wgemm_w<1, 16>(aH, Hv, W0v, w, lane);
        const int r0 = (w & 1) * 32 + (lane >> 2);
        const int col = (w >> 1) * 8 + 2 * (lane & 3);
        float bb0 = __ldg(qhb + col), bb1 = __ldg(qhb + col + 1);
#pragma unroll
        for (int mi = 0; mi < 2; ++mi)
#pragma unroll
            for (int hh = 0; hh < 2; ++hh) {
                int r = r0 + 16 * mi + 8 * hh;
                float2 v = make_float2(aH[mi][0][2 * hh] + bb0,
                                       aH[mi][0][2 * hh + 1] + bb1);
                *reinterpret_cast<float2*>(
                    out + (((size_t)b0 + (r >> 5)) * NAG + (r & 31)) * 32 + col) = v;
            }
    }
}

extern "C" void kernel_launch(void* const* d_in, const int* in_sizes, int n_in,
                              void* d_out, int out_size)
{
    cudaFuncSetAttribute(dgn_mma, cudaFuncAttributeMaxDynamicSharedMemorySize, SM_TOTAL);
    dgn_mma<<<2048, 256, SM_TOTAL>>>(
        (const float*)d_in[0],  (const float*)d_in[1],  (const float*)d_in[2],  (const float*)d_in[3],
        (const float*)d_in[4],  (const float*)d_in[5],  (const float*)d_in[6],  (const float*)d_in[7],
        (const float*)d_in[8],  (const float*)d_in[9],  (const float*)d_in[10], (const float*)d_in[11],
        (const float*)d_in[12], (const float*)d_in[13], (const float*)d_in[14], (const float*)d_in[15],
        (const float*)d_in[16], (const float*)d_in[17], (const float*)d_in[18], (const float*)d_in[19],
        (const float*)d_in[20], (const float*)d_in[21], (float*)d_out);
}

// round 6
// speedup vs baseline: 2.4803x; 1.0354x over previous
#include <cuda_runtime.h>
#include <cstdint>

#define NAG 32
#define HID 128

// smem: W0, W1 = 64KB weight tiles ([k][n], chunk-XOR swizzle);
//       H, T1, T2 = 32KB activation tiles ([m][k], SW swizzle)
#define W0OFF 0
#define W1OFF 65536
#define HOFF  131072
#define T1OFF 163840
#define T2OFF 196608
#define SM_TOTAL 229376

// activation tile swizzle: [row][col<128] f32, row stride 512B
__device__ __forceinline__ uint32_t SW(int r, int c) {
    return (uint32_t)(r * 512 + ((((c >> 2) ^ (r & 7)) << 4) | ((c & 3) << 2)));
}

__device__ __forceinline__ uint32_t s2u(const void* p) {
    uint32_t a;
    asm("{ .reg .u64 t; cvta.to.shared.u64 t, %1; cvt.u32.u64 %0, t; }" : "=r"(a) : "l"(p));
    return a;
}
__device__ __forceinline__ uint32_t f2tf(float f) {
    uint32_t u;
    asm("cvt.rna.tf32.f32 %0, %1;" : "=r"(u) : "f"(f));
    return u;
}
__device__ __forceinline__ uint32_t lds(uint32_t a) {
    uint32_t v;
    asm volatile("ld.shared.b32 %0, [%1];" : "=r"(v) : "r"(a));
    return v;
}
__device__ __forceinline__ float ldsf(uint32_t a) {
    float v;
    asm volatile("ld.shared.b32 %0, [%1];" : "=f"(v) : "r"(a));
    return v;
}
__device__ __forceinline__ void sts2(uint32_t a, uint32_t x, uint32_t y) {
    asm volatile("st.shared.v2.b32 [%0], {%1,%2};" :: "r"(a), "r"(x), "r"(y));
}
__device__ __forceinline__ void sts4(uint32_t a, uint32_t x, uint32_t y, uint32_t z, uint32_t w) {
    asm volatile("st.shared.v4.b32 [%0], {%1,%2,%3,%4};" :: "r"(a), "r"(x), "r"(y), "r"(z), "r"(w));
}

__device__ __forceinline__ void mma_tf32(float c[4], const uint32_t a[4], const uint32_t b[2]) {
    asm volatile("mma.sync.aligned.m16n8k8.row.col.f32.tf32.tf32.f32 "
        "{%0,%1,%2,%3}, {%4,%5,%6,%7}, {%8,%9}, {%0,%1,%2,%3};"
        : "+f"(c[0]), "+f"(c[1]), "+f"(c[2]), "+f"(c[3])
        : "r"(a[0]), "r"(a[1]), "r"(a[2]), "r"(a[3]), "r"(b[0]), "r"(b[1]));
}

template<int NFRAG>
__device__ __forceinline__ void zacc(float a[2][NFRAG][4]) {
#pragma unroll
    for (int i = 0; i < 2; ++i)
#pragma unroll
        for (int j = 0; j < NFRAG; ++j)
#pragma unroll
            for (int k = 0; k < 4; ++k) a[i][j][k] = 0.f;
}

// A fragment (m16k8) from activation tile
__device__ __forceinline__ void ldA(uint32_t a[4], uint32_t At, int r, int k0, int ctig) {
    a[0] = lds(At + SW(r,     k0 + ctig));
    a[1] = lds(At + SW(r + 8, k0 + ctig));
    a[2] = lds(At + SW(r,     k0 + ctig + 4));
    a[3] = lds(At + SW(r + 8, k0 + ctig + 4));
}

// per-thread constant byte offsets into a weight tile for B fragments
template<int NFRAG>
__device__ __forceinline__ void mk_bofs(uint32_t bofs[NFRAG], int nb, int gid, int ctig) {
#pragma unroll
    for (int nf = 0; nf < NFRAG; ++nf) {
        int n = nb + 8 * nf + gid;
        uint32_t ch = (uint32_t)(n >> 2) ^ ((uint32_t)ctig << 1);
        bofs[nf] = ch * 16u + (uint32_t)(n & 3) * 4u;
    }
}

// ---- single GEMM, B = weight tile [k][n] ----
template<int NFRAG, int KSTEPS>
__device__ __forceinline__ void wgemm_w(float acc[2][NFRAG][4], uint32_t At, uint32_t Bt,
                                        int w, int lane) {
    const int gid = lane >> 2, ctig = lane & 3;
    const int ar0 = (w & 1) * 32 + gid;
    const int nb = (w >> 1) * (8 * NFRAG);
    uint32_t bofs[NFRAG];
    mk_bofs<NFRAG>(bofs, nb, gid, ctig);
    const uint32_t kbase = Bt + (uint32_t)ctig * 512u;
#pragma unroll
    for (int s = 0; s < KSTEPS; ++s) {
        const int k0 = 8 * s;
        uint32_t a[2][4];
        ldA(a[0], At, ar0,      k0, ctig);
        ldA(a[1], At, ar0 + 16, k0, ctig);
        uint32_t b[NFRAG][2];
#pragma unroll
        for (int nf = 0; nf < NFRAG; ++nf) {
            b[nf][0] = lds(kbase + (uint32_t)k0 * 512u + bofs[nf]);
            b[nf][1] = lds(kbase + (uint32_t)(k0 + 4) * 512u + bofs[nf]);
        }
#pragma unroll
        for (int mi = 0; mi < 2; ++mi)
#pragma unroll
            for (int nf = 0; nf < NFRAG; ++nf)
                mma_tf32(acc[mi][nf], a[mi], b[nf]);
    }
}

// ---- fused dual GEMM: shared A, two weight-B streams (K and Q projections) ----
__device__ __forceinline__ void wgemm_kq(float aK[2][2][4], float aQ[2][2][4],
                                         uint32_t At, uint32_t B0, uint32_t B1,
                                         int w, int lane) {
    const int gid = lane >> 2, ctig = lane & 3;
    const int ar0 = (w & 1) * 32 + gid;
    const int nb = (w >> 1) * 16;
    uint32_t bofs[2];
    mk_bofs<2>(bofs, nb, gid, ctig);
    const uint32_t k0b = B0 + (uint32_t)ctig * 512u;
    const uint32_t k1b = B1 + (uint32_t)ctig * 512u;
#pragma unroll
    for (int s = 0; s < 16; ++s) {
        const int k0 = 8 * s;
        uint32_t a[2][4];
        ldA(a[0], At, ar0,      k0, ctig);
        ldA(a[1], At, ar0 + 16, k0, ctig);
        uint32_t bk[2][2], bq[2][2];
#pragma unroll
        for (int nf = 0; nf < 2; ++nf) {
            bk[nf][0] = lds(k0b + (uint32_t)k0 * 512u + bofs[nf]);
            bk[nf][1] = lds(k0b + (uint32_t)(k0 + 4) * 512u + bofs[nf]);
            bq[nf][0] = lds(k1b + (uint32_t)k0 * 512u + bofs[nf]);
            bq[nf][1] = lds(k1b + (uint32_t)(k0 + 4) * 512u + bofs[nf]);
        }
#pragma unroll
        for (int mi = 0; mi < 2; ++mi)
#pragma unroll
            for (int nf = 0; nf < 2; ++nf) {
                mma_tf32(aK[mi][nf], a[mi], bk[nf]);
                mma_tf32(aQ[mi][nf], a[mi], bq[nf]);
            }
    }
}

// ---- fused: V projection (A=h, B=weight) + scores (A=Q tile, B=K act tile [n][k]) ----
__device__ __forceinline__ void wgemm_vs(float aV[2][2][4], float aS[2][1][4],
                                         uint32_t Ah, uint32_t Wv, uint32_t Aq, uint32_t Bk,
                                         int w, int lane) {
    const int gid = lane >> 2, ctig = lane & 3;
    const int ar0 = (w & 1) * 32 + gid;
    const int nbV = (w >> 1) * 16;
    const int nS  = (w >> 1) * 8 + gid;
    uint32_t bofs[2];
    mk_bofs<2>(bofs, nbV, gid, ctig);
    const uint32_t kvb = Wv + (uint32_t)ctig * 512u;
#pragma unroll
    for (int s = 0; s < 16; ++s) {
        const int k0 = 8 * s;
        uint32_t a1[2][4], a2[2][4];
        ldA(a1[0], Ah, ar0,      k0, ctig);
        ldA(a1[1], Ah, ar0 + 16, k0, ctig);
        ldA(a2[0], Aq, ar0,      k0, ctig);
        ldA(a2[1], Aq, ar0 + 16, k0, ctig);
        uint32_t bv[2][2], bs[2];
#pragma unroll
        for (int nf = 0; nf < 2; ++nf) {
            bv[nf][0] = lds(kvb + (uint32_t)k0 * 512u + bofs[nf]);
            bv[nf][1] = lds(kvb + (uint32_t)(k0 + 4) * 512u + bofs[nf]);
        }
        bs[0] = lds(Bk + SW(nS, k0 + ctig));
        bs[1] = lds(Bk + SW(nS, k0 + ctig + 4));
#pragma unroll
        for (int mi = 0; mi < 2; ++mi) {
#pragma unroll
            for (int nf = 0; nf < 2; ++nf) mma_tf32(aV[mi][nf], a1[mi], bv[nf]);
            mma_tf32(aS[mi][0], a2[mi], bs);
        }
    }
}

// ---- PV: A = P tile, B = V act tile read transposed ([k][n] indexing), K=64 ----
__device__ __forceinline__ void wgemm_pv(float acc[2][2][4], uint32_t Ap, uint32_t Bv,
                                         int w, int lane) {
    const int gid = lane >> 2, ctig = lane & 3;
    const int ar0 = (w & 1) * 32 + gid;
    const int nb = (w >> 1) * 16;
#pragma unroll
    for (int s = 0; s < 8; ++s) {
        const int k0 = 8 * s;
        uint32_t a[2][4];
        ldA(a[0], Ap, ar0,      k0, ctig);
        ldA(a[1], Ap, ar0 + 16, k0, ctig);
        uint32_t b[2][2];
#pragma unroll
        for (int nf = 0; nf < 2; ++nf) {
            int n = nb + 8 * nf + gid;
            b[nf][0] = lds(Bv + SW(k0 + ctig,     n));
            b[nf][1] = lds(Bv + SW(k0 + ctig + 4, n));
        }
#pragma unroll
        for (int mi = 0; mi < 2; ++mi)
#pragma unroll
            for (int nf = 0; nf < 2; ++nf)
                mma_tf32(acc[mi][nf], a[mi], b[nf]);
    }
}

// ---- weight loader (16 warps): gmem [128][128] -> smem [k][n] XOR layout ----
__device__ __forceinline__ void wload(uint32_t dst, const float* Wg, int w, int lane) {
    float4 v[8];
#pragma unroll
    for (int i = 0; i < 8; ++i)
        v[i] = __ldg(reinterpret_cast<const float4*>(Wg + (size_t)(8 * w + i) * HID) + lane);
#pragma unroll
    for (int i = 0; i < 8; ++i) {
        int k = 8 * w + i;
        uint32_t ch = (uint32_t)lane ^ (((uint32_t)k & 3u) << 1);
        sts4(dst + (uint32_t)k * 512u + ch * 16u,
             f2tf(v[i].x), f2tf(v[i].y), f2tf(v[i].z), f2tf(v[i].w));
    }
}
// head weight [128][32] -> same layout (chunks 0..7 used)
__device__ __forceinline__ void wload_head(uint32_t dst, const float* Wg, int w, int lane) {
#pragma unroll
    for (int i = 0; i < 2; ++i) {
        int k = 8 * w + 4 * i + (lane >> 3);
        int c = lane & 7;
        float4 v = __ldg(reinterpret_cast<const float4*>(Wg + (size_t)k * 32) + c);
        uint32_t ch = (uint32_t)c ^ (((uint32_t)k & 3u) << 1);
        sts4(dst + (uint32_t)k * 512u + ch * 16u,
             f2tf(v.x), f2tf(v.y), f2tf(v.z), f2tf(v.w));
    }
}

// ---- epilogue: acc -> act tile (RAW keeps fp32 bits, else tf32-converted) ----
template<int NFRAG, bool RAW>
__device__ __forceinline__ void epi(uint32_t dst, float acc[2][NFRAG][4], const float* bias,
                                    bool relu, int w, int lane) {
    const int r0 = (w & 1) * 32 + (lane >> 2);
    const int nc0 = (w >> 1) * (8 * NFRAG);
#pragma unroll
    for (int mi = 0; mi < 2; ++mi)
#pragma unroll
        for (int nf = 0; nf < NFRAG; ++nf) {
            int col = nc0 + 8 * nf + 2 * (lane & 3);
            float bb0 = bias ? __ldg(bias + col)     : 0.f;
            float bb1 = bias ? __ldg(bias + col + 1) : 0.f;
#pragma unroll
            for (int hh = 0; hh < 2; ++hh) {
                int r = r0 + 16 * mi + 8 * hh;
                float v0 = acc[mi][nf][2 * hh + 0] + bb0;
                float v1 = acc[mi][nf][2 * hh + 1] + bb1;
                if (relu) { v0 = fmaxf(v0, 0.f); v1 = fmaxf(v1, 0.f); }
                uint32_t u0 = RAW ? __float_as_uint(v0) : f2tf(v0);
                uint32_t u1 = RAW ? __float_as_uint(v1) : f2tf(v1);
                sts2(dst + SW(r, col), u0, u1);
            }
        }
}

// softmax over the two 32x32 diagonal blocks; P (tf32) written, off-diag zeroed
__device__ __forceinline__ void softmax2(uint32_t t1, const float* mask, int b0,
                                         int w, int lane) {
    const int i = 32 * w + lane, g = w;
    const float* mrow = mask + ((size_t)(b0 + g) * NAG + lane) * NAG;
    float l[32];
    float mx = -3.4e38f;
#pragma unroll
    for (int j = 0; j < 32; ++j) {
        float s = ldsf(t1 + SW(i, 32 * g + j));
        float m = __ldg(mrow + j);
        float v = s * m - 9e15f * (1.0f - m);
        l[j] = v;
        mx = fmaxf(mx, v);
    }
    float sum = 0.f;
#pragma unroll
    for (int j = 0; j < 32; ++j) { float e = __expf(l[j] - mx); l[j] = e; sum += e; }
    float inv = 1.0f / sum;
#pragma unroll
    for (int j = 0; j < 32; j += 2) {
        sts2(t1 + SW(i, 32 * g + j), f2tf(l[j] * inv), f2tf(l[j + 1] * inv));
        sts2(t1 + SW(i, 32 * (1 - g) + j), 0u, 0u);
    }
}

// one attention block; kw in W0, qw in W1 on entry; prefetches nw1->W0, nw2->W1
template<bool LAST>
__device__ __forceinline__ void att_block(
    uint32_t H, uint32_t T1, uint32_t T2, uint32_t W0, uint32_t W1,
    const float* kb, const float* qb, const float* vw, const float* vb,
    const float* ow, const float* ob, const float* nw1, const float* nw2,
    const float* mask, int b0, int w, int lane)
{
    {
        float aK[2][2][4], aQ[2][2][4];
        zacc<2>(aK); zacc<2>(aQ);
        wgemm_kq(aK, aQ, H, W0, W1, w, lane);
        __syncthreads();
        wload(W0, vw, w, lane);
        wload(W1, ow, w, lane);
        epi<2, false>(T1, aK, kb, true, w, lane);   // K -> T1 ([j][h])
        epi<2, false>(T2, aQ, qb, true, w, lane);   // Q -> T2 ([i][h])
        __syncthreads();
    }
    {
        float aV[2][2][4]; float aS[2][1][4];
        zacc<2>(aV); zacc<1>(aS);
        wgemm_vs(aV, aS, H, W0, T2, T1, w, lane);
        __syncthreads();
        if (LAST) wload_head(W0, nw1, w, lane); else wload(W0, nw1, w, lane);
        epi<2, false>(H, aV, vb, true, w, lane);    // V -> H ([j][h])
        epi<1, true>(T1, aS, nullptr, false, w, lane); // raw logits -> T1
        __syncthreads();
    }
    if (w < 2) softmax2(T1, mask, b0, w, lane);     // P -> T1 ([i][j], tf32)
    __syncthreads();
    {
        float aP[2][2][4]; zacc<2>(aP);
        wgemm_pv(aP, T1, H, w, lane);               // PV -> acc
        __syncthreads();
        epi<2, false>(T2, aP, nullptr, false, w, lane); // PV -> T2
        __syncthreads();
    }
    {
        float aO[2][2][4]; zacc<2>(aO);
        wgemm_w<2, 16>(aO, T2, W1, w, lane);        // out-proj
        __syncthreads();
        if (!LAST) wload(W1, nw2, w, lane);
        epi<2, false>(H, aO, ob, true, w, lane);    // h' -> H
        __syncthreads();
    }
}

__global__ void __launch_bounds__(512, 1)
dgn_mma(const float* __restrict__ x, const float* __restrict__ mask,
        const float* __restrict__ enc_w, const float* __restrict__ enc_b,
        const float* __restrict__ a1_vw, const float* __restrict__ a1_vb,
        const float* __restrict__ a1_kw, const float* __restrict__ a1_kb,
        const float* __restrict__ a1_qw, const float* __restrict__ a1_qb,
        const float* __restrict__ a1_ow, const float* __restrict__ a1_ob,
        const float* __restrict__ a2_vw, const float* __restrict__ a2_vb,
        const float* __restrict__ a2_kw, const float* __restrict__ a2_kb,
        const float* __restrict__ a2_qw, const float* __restrict__ a2_qb,
        const float* __restrict__ a2_ow, const float* __restrict__ a2_ob,
        const float* __restrict__ qhw, const float* __restrict__ qhb,
        float* __restrict__ out)
{
    extern __shared__ __align__(16) char sm[];
    const uint32_t base = s2u(sm);
    const uint32_t W0v = base + W0OFF, W1v = base + W1OFF;
    const uint32_t Hv = base + HOFF, T1v = base + T1OFF, T2v = base + T2OFF;
    const int tid = threadIdx.x, w = tid >> 5, lane = tid & 31;
    const int b0 = blockIdx.x * 2;

    // ---- load x (tf32) into T1 (cols 0..127) / T2 (cols 128..255); enc weights ----
#pragma unroll
    for (int it = 0; it < 8; ++it) {
        int idx = tid + 512 * it;
        int r = idx >> 6, ch = idx & 63;
        int col = 4 * ch;
        float4 v = *reinterpret_cast<const float4*>(
            x + (((size_t)b0 + (r >> 5)) * NAG + (r & 31)) * 256 + col);
        uint32_t dst = (col < 128 ? T1v : T2v) + SW(r, col & 127);
        sts4(dst, f2tf(v.x), f2tf(v.y), f2tf(v.z), f2tf(v.w));
    }
    wload(W0v, enc_w, w, lane);
    wload(W1v, enc_w + 128 * HID, w, lane);
    __syncthreads();

    // ---- encoder: h1 = relu(x @ enc_w + enc_b), K=256 ----
    {
        float aE[2][2][4]; zacc<2>(aE);
        wgemm_w<2, 16>(aE, T1v, W0v, w, lane);
        wgemm_w<2, 16>(aE, T2v, W1v, w, lane);
        __syncthreads();
        wload(W0v, a1_kw, w, lane);
        wload(W1v, a1_qw, w, lane);
        epi<2, false>(Hv, aE, enc_b, true, w, lane);
        __syncthreads();
    }

    att_block<false>(Hv, T1v, T2v, W0v, W1v,
                     a1_kb, a1_qb, a1_vw, a1_vb, a1_ow, a1_ob,
                     a2_kw, a2_qw, mask, b0, w, lane);
    att_block<true>(Hv, T1v, T2v, W0v, W1v,
                    a2_kb, a2_qb, a2_vw, a2_vb, a2_ow, a2_ob,
                    qhw, nullptr, mask, b0, w, lane);

    // ---- head: q = h3 @ q_w + q_b (N=32); N-groups 0..3 write out ----
    {
        float aH[2][1][4]; zacc<1>(aH);
        wgemm_w<1, 16>(aH, Hv, W0v, w, lane);
        if ((w >> 1) < 4) {
            const int r0 = (w & 1) * 32 + (lane >> 2);
            const int col = (w >> 1) * 8 + 2 * (lane & 3);
            float bb0 = __ldg(qhb + col), bb1 = __ldg(qhb + col + 1);
#pragma unroll
            for (int mi = 0; mi < 2; ++mi)
#pragma unroll
                for (int hh = 0; hh < 2; ++hh) {
                    int r = r0 + 16 * mi + 8 * hh;
                    float2 v = make_float2(aH[mi][0][2 * hh] + bb0,
                                           aH[mi][0][2 * hh + 1] + bb1);
                    *reinterpret_cast<float2*>(
                        out + (((size_t)b0 + (r >> 5)) * NAG + (r & 31)) * 32 + col) = v;
                }
        }
    }
}

extern "C" void kernel_launch(void* const* d_in, const int* in_sizes, int n_in,
                              void* d_out, int out_size)
{
    cudaFuncSetAttribute(dgn_mma, cudaFuncAttributeMaxDynamicSharedMemorySize, SM_TOTAL);
    dgn_mma<<<2048, 512, SM_TOTAL>>>(
        (const float*)d_in[0],  (const float*)d_in[1],  (const float*)d_in[2],  (const float*)d_in[3],
        (const float*)d_in[4],  (const float*)d_in[5],  (const float*)d_in[6],  (const float*)d_in[7],
        (const float*)d_in[8],  (const float*)d_in[9],  (const float*)d_in[10], (const float*)d_in[11],
        (const float*)d_in[12], (const float*)d_in[13], (const float*)d_in[14], (const float*)d_in[15],
        (const float*)d_in[16], (const float*)d_in[17], (const float*)d_in[18], (const float*)d_in[19],
        (const float*)d_in[20], (const float*)d_in[21], (float*)d_out);
}

// round 7
// speedup vs baseline: 2.6910x; 1.0850x over previous
#include <cuda_runtime.h>
#include <cstdint>

#define NAG 32
#define HID 128

#define W0OFF 0
#define W1OFF 65536
#define HOFF  131072
#define T1OFF 163840
#define T2OFF 196608
#define SM_TOTAL 229376

// activation/weight tile swizzle: [row][col<128] f32, row stride 512B, 16B-chunk XOR
__device__ __forceinline__ uint32_t SW(int r, int c) {
    return (uint32_t)(r * 512 + ((((c >> 2) ^ (r & 7)) << 4) | ((c & 3) << 2)));
}

__device__ __forceinline__ uint32_t s2u(const void* p) {
    uint32_t a;
    asm("{ .reg .u64 t; cvta.to.shared.u64 t, %1; cvt.u32.u64 %0, t; }" : "=r"(a) : "l"(p));
    return a;
}
__device__ __forceinline__ uint32_t f2tf(float f) {
    uint32_t u;
    asm("cvt.rna.tf32.f32 %0, %1;" : "=r"(u) : "f"(f));
    return u;
}
__device__ __forceinline__ uint32_t lds(uint32_t a) {
    uint32_t v;
    asm volatile("ld.shared.b32 %0, [%1];" : "=r"(v) : "r"(a));
    return v;
}
__device__ __forceinline__ float ldsf(uint32_t a) {
    float v;
    asm volatile("ld.shared.b32 %0, [%1];" : "=f"(v) : "r"(a));
    return v;
}
__device__ __forceinline__ void sts2(uint32_t a, uint32_t x, uint32_t y) {
    asm volatile("st.shared.v2.b32 [%0], {%1,%2};" :: "r"(a), "r"(x), "r"(y));
}
__device__ __forceinline__ void sts4(uint32_t a, uint32_t x, uint32_t y, uint32_t z, uint32_t w) {
    asm volatile("st.shared.v4.b32 [%0], {%1,%2,%3,%4};" :: "r"(a), "r"(x), "r"(y), "r"(z), "r"(w));
}
// ldmatrix x4: 4 8x8-b16 tiles == 4 8x4-f32 tiles; lane mapping == tf32 MMA fragments
__device__ __forceinline__ void ldsm4(uint32_t a[4], uint32_t addr) {
    asm volatile("ldmatrix.sync.aligned.m8n8.x4.shared.b16 {%0,%1,%2,%3}, [%4];"
        : "=r"(a[0]), "=r"(a[1]), "=r"(a[2]), "=r"(a[3]) : "r"(addr));
}

__device__ __forceinline__ void mma_tf32(float c[4], const uint32_t a[4], const uint32_t b[2]) {
    asm volatile("mma.sync.aligned.m16n8k8.row.col.f32.tf32.tf32.f32 "
        "{%0,%1,%2,%3}, {%4,%5,%6,%7}, {%8,%9}, {%0,%1,%2,%3};"
        : "+f"(c[0]), "+f"(c[1]), "+f"(c[2]), "+f"(c[3])
        : "r"(a[0]), "r"(a[1]), "r"(a[2]), "r"(a[3]), "r"(b[0]), "r"(b[1]));
}

template<int NFRAG>
__device__ __forceinline__ void zacc(float a[2][NFRAG][4]) {
#pragma unroll
    for (int i = 0; i < 2; ++i)
#pragma unroll
        for (int j = 0; j < NFRAG; ++j)
#pragma unroll
            for (int k = 0; k < 4; ++k) a[i][j][k] = 0.f;
}

// per-lane A-fragment ldmatrix geometry for a 64-row tile, warp m-group (w&1)
// lane i covers tile t=i>>3: row = r0 + (t&1)*8 + (i&7), col-half tc = (i>>4)&1
#define A_GEOM(At, w, lane)                                              \
    const int _arow = (w & 1) * 32 + (((lane) >> 3) & 1) * 8 + ((lane) & 7); \
    const uint32_t abase = (At) + (uint32_t)_arow * 512u;                \
    const uint32_t arx = (uint32_t)(_arow & 7);                          \
    const uint32_t atc = (uint32_t)(((lane) >> 4) & 1)

// per-thread constant byte offsets into a weight tile [k][n] for B fragments
template<int NFRAG>
__device__ __forceinline__ void mk_bofs(uint32_t bofs[NFRAG], int nb, int gid, int ctig) {
#pragma unroll
    for (int nf = 0; nf < NFRAG; ++nf) {
        int n = nb + 8 * nf + gid;
        uint32_t ch = (uint32_t)(n >> 2) ^ ((uint32_t)ctig << 1);
        bofs[nf] = ch * 16u + (uint32_t)(n & 3) * 4u;
    }
}

// ---- single GEMM, B = weight tile [k][n] ----
template<int NFRAG, int KSTEPS>
__device__ __forceinline__ void wgemm_w(float acc[2][NFRAG][4], uint32_t At, uint32_t Bt,
                                        int w, int lane) {
    const int gid = lane >> 2, ctig = lane & 3;
    A_GEOM(At, w, lane);
    const int nb = (w >> 1) * (8 * NFRAG);
    uint32_t bofs[NFRAG];
    mk_bofs<NFRAG>(bofs, nb, gid, ctig);
    const uint32_t kbase = Bt + (uint32_t)ctig * 512u;
#pragma unroll
    for (int s = 0; s < KSTEPS; ++s) {
        const uint32_t ao = (((2u * (uint32_t)s + atc) ^ arx) << 4);
        uint32_t a0[4], a1[4];
        ldsm4(a0, abase + ao);
        ldsm4(a1, abase + 8192u + ao);
        const int k0 = 8 * s;
        uint32_t b[NFRAG][2];
#pragma unroll
        for (int nf = 0; nf < NFRAG; ++nf) {
            b[nf][0] = lds(kbase + (uint32_t)k0 * 512u + bofs[nf]);
            b[nf][1] = lds(kbase + (uint32_t)(k0 + 4) * 512u + bofs[nf]);
        }
#pragma unroll
        for (int nf = 0; nf < NFRAG; ++nf) {
            mma_tf32(acc[0][nf], a0, b[nf]);
            mma_tf32(acc[1][nf], a1, b[nf]);
        }
    }
}

// ---- fused dual GEMM: shared A, two weight-B streams (K and Q projections) ----
__device__ __forceinline__ void wgemm_kq(float aK[2][2][4], float aQ[2][2][4],
                                         uint32_t At, uint32_t B0, uint32_t B1,
                                         int w, int lane) {
    const int gid = lane >> 2, ctig = lane & 3;
    A_GEOM(At, w, lane);
    const int nb = (w >> 1) * 16;
    uint32_t bofs[2];
    mk_bofs<2>(bofs, nb, gid, ctig);
    const uint32_t k0b = B0 + (uint32_t)ctig * 512u;
    const uint32_t k1b = B1 + (uint32_t)ctig * 512u;
#pragma unroll
    for (int s = 0; s < 16; ++s) {
        const uint32_t ao = (((2u * (uint32_t)s + atc) ^ arx) << 4);
        uint32_t a0[4], a1[4];
        ldsm4(a0, abase + ao);
        ldsm4(a1, abase + 8192u + ao);
        const int k0 = 8 * s;
        uint32_t bk[2][2], bq[2][2];
#pragma unroll
        for (int nf = 0; nf < 2; ++nf) {
            bk[nf][0] = lds(k0b + (uint32_t)k0 * 512u + bofs[nf]);
            bk[nf][1] = lds(k0b + (uint32_t)(k0 + 4) * 512u + bofs[nf]);
            bq[nf][0] = lds(k1b + (uint32_t)k0 * 512u + bofs[nf]);
            bq[nf][1] = lds(k1b + (uint32_t)(k0 + 4) * 512u + bofs[nf]);
        }
#pragma unroll
        for (int nf = 0; nf < 2; ++nf) {
            mma_tf32(aK[0][nf], a0, bk[nf]);
            mma_tf32(aK[1][nf], a1, bk[nf]);
            mma_tf32(aQ[0][nf], a0, bq[nf]);
            mma_tf32(aQ[1][nf], a1, bq[nf]);
        }
    }
}

// ---- fused: V projection (all warps) + diagonal-block scores (warps 0..7) ----
// scores: warp computes its batch's rows x n-slice nS0..nS0+7 (B = K tile via ldmatrix)
__device__ __forceinline__ void wgemm_vs(float aV[2][2][4], float aS[2][1][4],
                                         uint32_t Ah, uint32_t Wv, uint32_t Aq, uint32_t Bk,
                                         int w, int lane) {
    const int gid = lane >> 2, ctig = lane & 3;
    A_GEOM(Ah, w, lane);
    const uint32_t qbase = Aq + (uint32_t)_arow * 512u;
    const int nbV = (w >> 1) * 16;
    uint32_t bofs[2];
    mk_bofs<2>(bofs, nbV, gid, ctig);
    const uint32_t kvb = Wv + (uint32_t)ctig * 512u;
    // scores B geometry: tiles t=lane>>3 cover chunk 2s+t (two k-steps per x4)
    const int nS0 = (w & 1) * 32 + (w >> 1) * 8;
    const int brow = nS0 + (lane & 7);
    const uint32_t sbase = Bk + (uint32_t)brow * 512u;
    const uint32_t brx = (uint32_t)(brow & 7);
    const uint32_t btc = (uint32_t)(lane >> 3);
    uint32_t bs[4];
#pragma unroll
    for (int s = 0; s < 16; ++s) {
        const uint32_t ao = (((2u * (uint32_t)s + atc) ^ arx) << 4);
        uint32_t a0[4], a1[4];
        ldsm4(a0, abase + ao);
        ldsm4(a1, abase + 8192u + ao);
        const int k0 = 8 * s;
        uint32_t bv[2][2];
#pragma unroll
        for (int nf = 0; nf < 2; ++nf) {
            bv[nf][0] = lds(kvb + (uint32_t)k0 * 512u + bofs[nf]);
            bv[nf][1] = lds(kvb + (uint32_t)(k0 + 4) * 512u + bofs[nf]);
        }
        if (w < 8) {
            uint32_t q0[4], q1[4];
            ldsm4(q0, qbase + ao);
            ldsm4(q1, qbase + 8192u + ao);
            if ((s & 1) == 0)
                ldsm4(bs, sbase + (((2u * (uint32_t)s + btc) ^ brx) << 4));
            const uint32_t* bp = bs + 2 * (s & 1);
            mma_tf32(aS[0][0], q0, bp);
            mma_tf32(aS[1][0], q1, bp);
        }
#pragma unroll
        for (int nf = 0; nf < 2; ++nf) {
            mma_tf32(aV[0][nf], a0, bv[nf]);
            mma_tf32(aV[1][nf], a1, bv[nf]);
        }
    }
}

// ---- PV (diagonal): A = P rows of own batch, K=32 (own batch cols); B = V [j][h] ----
__device__ __forceinline__ void wgemm_pv(float acc[2][2][4], uint32_t Ap, uint32_t Bv,
                                         int w, int lane) {
    const int gid = lane >> 2, ctig = lane & 3;
    A_GEOM(Ap, w, lane);
    const int nb = (w >> 1) * 16;
    const int kbch = 8 * (w & 1);          // chunk base for k-offset 32*(w&1)
#pragma unroll
    for (int s = 0; s < 4; ++s) {
        const uint32_t ao = ((((uint32_t)(kbch + 2 * s) + atc) ^ arx) << 4);
        uint32_t a0[4], a1[4];
        ldsm4(a0, abase + ao);
        ldsm4(a1, abase + 8192u + ao);
        const int k0 = 32 * (w & 1) + 8 * s;
        uint32_t b[2][2];
#pragma unroll
        for (int nf = 0; nf < 2; ++nf) {
            int n = nb + 8 * nf + gid;
            b[nf][0] = lds(Bv + SW(k0 + ctig,     n));
            b[nf][1] = lds(Bv + SW(k0 + ctig + 4, n));
        }
#pragma unroll
        for (int nf = 0; nf < 2; ++nf) {
            mma_tf32(acc[0][nf], a0, b[nf]);
            mma_tf32(acc[1][nf], a1, b[nf]);
        }
    }
}

// ---- weight loader (16 warps): gmem [128][128] -> smem [k][n] XOR layout ----
__device__ __forceinline__ void wload(uint32_t dst, const float* Wg, int w, int lane) {
    float4 v[8];
#pragma unroll
    for (int i = 0; i < 8; ++i)
        v[i] = __ldg(reinterpret_cast<const float4*>(Wg + (size_t)(8 * w + i) * HID) + lane);
#pragma unroll
    for (int i = 0; i < 8; ++i) {
        int k = 8 * w + i;
        uint32_t ch = (uint32_t)lane ^ (((uint32_t)k & 3u) << 1);
        sts4(dst + (uint32_t)k * 512u + ch * 16u,
             f2tf(v[i].x), f2tf(v[i].y), f2tf(v[i].z), f2tf(v[i].w));
    }
}
__device__ __forceinline__ void wload_head(uint32_t dst, const float* Wg, int w, int lane) {
#pragma unroll
    for (int i = 0; i < 2; ++i) {
        int k = 8 * w + 4 * i + (lane >> 3);
        int c = lane & 7;
        float4 v = __ldg(reinterpret_cast<const float4*>(Wg + (size_t)k * 32) + c);
        uint32_t ch = (uint32_t)c ^ (((uint32_t)k & 3u) << 1);
        sts4(dst + (uint32_t)k * 512u + ch * 16u,
             f2tf(v.x), f2tf(v.y), f2tf(v.z), f2tf(v.w));
    }
}

// ---- epilogue: acc -> act tile (tf32-converted) ----
template<int NFRAG>
__device__ __forceinline__ void epi(uint32_t dst, float acc[2][NFRAG][4], const float* bias,
                                    bool relu, int w, int lane) {
    const int r0 = (w & 1) * 32 + (lane >> 2);
    const int nc0 = (w >> 1) * (8 * NFRAG);
#pragma unroll
    for (int mi = 0; mi < 2; ++mi)
#pragma unroll
        for (int nf = 0; nf < NFRAG; ++nf) {
            int col = nc0 + 8 * nf + 2 * (lane & 3);
            float bb0 = bias ? __ldg(bias + col)     : 0.f;
            float bb1 = bias ? __ldg(bias + col + 1) : 0.f;
#pragma unroll
            for (int hh = 0; hh < 2; ++hh) {
                int r = r0 + 16 * mi + 8 * hh;
                float v0 = acc[mi][nf][2 * hh + 0] + bb0;
                float v1 = acc[mi][nf][2 * hh + 1] + bb1;
                if (relu) { v0 = fmaxf(v0, 0.f); v1 = fmaxf(v1, 0.f); }
                sts2(dst + SW(r, col), f2tf(v0), f2tf(v1));
            }
        }
}

// scores epilogue: raw fp32 logits -> T1 diag block (warps 0..7 only)
__device__ __forceinline__ void epi_scores(uint32_t dst, float aS[2][1][4], int w, int lane) {
    if (w >= 8) return;
    const int r0 = (w & 1) * 32 + (lane >> 2);
    const int col = (w & 1) * 32 + (w >> 1) * 8 + 2 * (lane & 3);
#pragma unroll
    for (int mi = 0; mi < 2; ++mi)
#pragma unroll
        for (int hh = 0; hh < 2; ++hh) {
            int r = r0 + 16 * mi + 8 * hh;
            sts2(dst + SW(r, col),
                 __float_as_uint(aS[mi][0][2 * hh]),
                 __float_as_uint(aS[mi][0][2 * hh + 1]));
        }
}

// softmax over the two 32x32 diagonal blocks; P (tf32) written to same cols
__device__ __forceinline__ void softmax2(uint32_t t1, const float* mask, int b0,
                                         int w, int lane) {
    const int i = 32 * w + lane, g = w;
    const float* mrow = mask + ((size_t)(b0 + g) * NAG + lane) * NAG;
    float l[32];
    float mx = -3.4e38f;
#pragma unroll
    for (int j = 0; j < 32; ++j) {
        float s = ldsf(t1 + SW(i, 32 * g + j));
        float m = __ldg(mrow + j);
        float v = s * m - 9e15f * (1.0f - m);
        l[j] = v;
        mx = fmaxf(mx, v);
    }
    float sum = 0.f;
#pragma unroll
    for (int j = 0; j < 32; ++j) { float e = __expf(l[j] - mx); l[j] = e; sum += e; }
    float inv = 1.0f / sum;
#pragma unroll
    for (int j = 0; j < 32; j += 2)
        sts2(t1 + SW(i, 32 * g + j), f2tf(l[j] * inv), f2tf(l[j + 1] * inv));
}

template<bool LAST>
__device__ __forceinline__ void att_block(
    uint32_t H, uint32_t T1, uint32_t T2, uint32_t W0, uint32_t W1,
    const float* kb, const float* qb, const float* vw, const float* vb,
    const float* ow, const float* ob, const float* nw1, const float* nw2,
    const float* mask, int b0, int w, int lane)
{
    {
        float aK[2][2][4], aQ[2][2][4];
        zacc<2>(aK); zacc<2>(aQ);
        wgemm_kq(aK, aQ, H, W0, W1, w, lane);
        __syncthreads();
        wload(W0, vw, w, lane);
        wload(W1, ow, w, lane);
        epi<2>(T1, aK, kb, true, w, lane);   // K -> T1 ([j][h])
        epi<2>(T2, aQ, qb, true, w, lane);   // Q -> T2 ([i][h])
        __syncthreads();
    }
    {
        float aV[2][2][4]; float aS[2][1][4];
        zacc<2>(aV); zacc<1>(aS);
        wgemm_vs(aV, aS, H, W0, T2, T1, w, lane);
        __syncthreads();
        if (LAST) wload_head(W0, nw1, w, lane); else wload(W0, nw1, w, lane);
        epi<2>(H, aV, vb, true, w, lane);    // V -> H ([j][h])
        epi_scores(T1, aS, w, lane);         // raw diag logits -> T1
        __syncthreads();
    }
    if (w < 2) softmax2(T1, mask, b0, w, lane);  // P -> T1 diag (tf32)
    __syncthreads();
    {
        float aP[2][2][4]; zacc<2>(aP);
        wgemm_pv(aP, T1, H, w, lane);        // diag PV, K=32
        __syncthreads();
        epi<2>(T2, aP, nullptr, false, w, lane);
        __syncthreads();
    }
    {
        float aO[2][2][4]; zacc<2>(aO);
        wgemm_w<2, 16>(aO, T2, W1, w, lane);
        __syncthreads();
        if (!LAST) wload(W1, nw2, w, lane);
        epi<2>(H, aO, ob, true, w, lane);    // h' -> H
        __syncthreads();
    }
}

__global__ void __launch_bounds__(512, 1)
dgn_mma(const float* __restrict__ x, const float* __restrict__ mask,
        const float* __restrict__ enc_w, const float* __restrict__ enc_b,
        const float* __restrict__ a1_vw, const float* __restrict__ a1_vb,
        const float* __restrict__ a1_kw, const float* __restrict__ a1_kb,
        const float* __restrict__ a1_qw, const float* __restrict__ a1_qb,
        const float* __restrict__ a1_ow, const float* __restrict__ a1_ob,
        const float* __restrict__ a2_vw, const float* __restrict__ a2_vb,
        const float* __restrict__ a2_kw, const float* __restrict__ a2_kb,
        const float* __restrict__ a2_qw, const float* __restrict__ a2_qb,
        const float* __restrict__ a2_ow, const float* __restrict__ a2_ob,
        const float* __restrict__ qhw, const float* __restrict__ qhb,
        float* __restrict__ out)
{
    extern __shared__ __align__(16) char sm[];
    const uint32_t base = s2u(sm);
    const uint32_t W0v = base + W0OFF, W1v = base + W1OFF;
    const uint32_t Hv = base + HOFF, T1v = base + T1OFF, T2v = base + T2OFF;
    const int tid = threadIdx.x, w = tid >> 5, lane = tid & 31;
    const int b0 = blockIdx.x * 2;

#pragma unroll
    for (int it = 0; it < 8; ++it) {
        int idx = tid + 512 * it;
        int r = idx >> 6, ch = idx & 63;
        int col = 4 * ch;
        float4 v = *reinterpret_cast<const float4*>(
            x + (((size_t)b0 + (r >> 5)) * NAG + (r & 31)) * 256 + col);
        uint32_t dst = (col < 128 ? T1v : T2v) + SW(r, col & 127);
        sts4(dst, f2tf(v.x), f2tf(v.y), f2tf(v.z), f2tf(v.w));
    }
    wload(W0v, enc_w, w, lane);
    wload(W1v, enc_w + 128 * HID, w, lane);
    __syncthreads();

    {
        float aE[2][2][4]; zacc<2>(aE);
        wgemm_w<2, 16>(aE, T1v, W0v, w, lane);
        wgemm_w<2, 16>(aE, T2v, W1v, w, lane);
        __syncthreads();
        wload(W0v, a1_kw, w, lane);
        wload(W1v, a1_qw, w, lane);
        epi<2>(Hv, aE, enc_b, true, w, lane);
        __syncthreads();
    }

    att_block<false>(Hv, T1v, T2v, W0v, W1v,
                     a1_kb, a1_qb, a1_vw, a1_vb, a1_ow, a1_ob,
                     a2_kw, a2_qw, mask, b0, w, lane);
    att_block<true>(Hv, T1v, T2v, W0v, W1v,
                    a2_kb, a2_qb, a2_vw, a2_vb, a2_ow, a2_ob,
                    qhw, nullptr, mask, b0, w, lane);

    {
        float aH[2][1][4]; zacc<1>(aH);
        wgemm_w<1, 16>(aH, Hv, W0v, w, lane);
        if ((w >> 1) < 4) {
            const int r0 = (w & 1) * 32 + (lane >> 2);
            const int col = (w >> 1) * 8 + 2 * (lane & 3);
            float bb0 = __ldg(qhb + col), bb1 = __ldg(qhb + col + 1);
#pragma unroll
            for (int mi = 0; mi < 2; ++mi)
#pragma unroll
                for (int hh = 0; hh < 2; ++hh) {
                    int r = r0 + 16 * mi + 8 * hh;
                    float2 v = make_float2(aH[mi][0][2 * hh] + bb0,
                                           aH[mi][0][2 * hh + 1] + bb1);
                    *reinterpret_cast<float2*>(
                        out + (((size_t)b0 + (r >> 5)) * NAG + (r & 31)) * 32 + col) = v;
                }
        }
    }
}

extern "C" void kernel_launch(void* const* d_in, const int* in_sizes, int n_in,
                              void* d_out, int out_size)
{
    cudaFuncSetAttribute(dgn_mma, cudaFuncAttributeMaxDynamicSharedMemorySize, SM_TOTAL);
    dgn_mma<<<2048, 512, SM_TOTAL>>>(
        (const float*)d_in[0],  (const float*)d_in[1],  (const float*)d_in[2],  (const float*)d_in[3],
        (const float*)d_in[4],  (const float*)d_in[5],  (const float*)d_in[6],  (const float*)d_in[7],
        (const float*)d_in[8],  (const float*)d_in[9],  (const float*)d_in[10], (const float*)d_in[11],
        (const float*)d_in[12], (const float*)d_in[13], (const float*)d_in[14], (const float*)d_in[15],
        (const float*)d_in[16], (const float*)d_in[17], (const float*)d_in[18], (const float*)d_in[19],
        (const float*)d_in[20], (const float*)d_in[21], (float*)d_out);
}

// round 8
// speedup vs baseline: 5.8263x; 2.1651x over previous
#include <cuda_runtime.h>
#include <cuda_fp16.h>
#include <cstdint>

// smem (bytes): W0,W1 = 32KB f16 weight tiles [k=128][n=128]; H,T1,T2 = 16KB f16 act tiles [64][128]
#define W0OFF 0
#define W1OFF 32768
#define HOFF  65536
#define T1OFF 81920
#define T2OFF 98304
#define SM_TOTAL 114688   // 112KB -> 2 CTAs/SM

// f16 tile swizzle: [row][col] (128 cols), row stride 256B, 16B-chunk XOR
__device__ __forceinline__ uint32_t AS(int r, int c) {
    return (uint32_t)(r * 256 + (((c >> 3) ^ (r & 7)) << 4) + (c & 7) * 2);
}
__device__ __forceinline__ uint32_t s2u(const void* p) {
    uint32_t a;
    asm("{ .reg .u64 t; cvta.to.shared.u64 t, %1; cvt.u32.u64 %0, t; }" : "=r"(a) : "l"(p));
    return a;
}
__device__ __forceinline__ uint32_t pack2(float a, float b) {
    __half2 h = __floats2half2_rn(a, b);
    return *reinterpret_cast<uint32_t*>(&h);
}
__device__ __forceinline__ void sts32(uint32_t a, uint32_t v) {
    asm volatile("st.shared.b32 [%0], %1;" :: "r"(a), "r"(v));
}
__device__ __forceinline__ void sts64(uint32_t a, uint32_t x, uint32_t y) {
    asm volatile("st.shared.v2.b32 [%0], {%1,%2};" :: "r"(a), "r"(x), "r"(y));
}
__device__ __forceinline__ void ldsm4(uint32_t r[4], uint32_t a) {
    asm volatile("ldmatrix.sync.aligned.m8n8.x4.shared.b16 {%0,%1,%2,%3}, [%4];"
        : "=r"(r[0]), "=r"(r[1]), "=r"(r[2]), "=r"(r[3]) : "r"(a));
}
__device__ __forceinline__ void ldsm4t(uint32_t r[4], uint32_t a) {
    asm volatile("ldmatrix.sync.aligned.m8n8.x4.trans.shared.b16 {%0,%1,%2,%3}, [%4];"
        : "=r"(r[0]), "=r"(r[1]), "=r"(r[2]), "=r"(r[3]) : "r"(a));
}
__device__ __forceinline__ void ldsm2t(uint32_t r[2], uint32_t a) {
    asm volatile("ldmatrix.sync.aligned.m8n8.x2.trans.shared.b16 {%0,%1}, [%2];"
        : "=r"(r[0]), "=r"(r[1]) : "r"(a));
}
__device__ __forceinline__ void mma16(float c[4], const uint32_t a[4], uint32_t b0, uint32_t b1) {
    asm volatile("mma.sync.aligned.m16n8k16.row.col.f32.f16.f16.f32 "
        "{%0,%1,%2,%3}, {%4,%5,%6,%7}, {%8,%9}, {%0,%1,%2,%3};"
        : "+f"(c[0]), "+f"(c[1]), "+f"(c[2]), "+f"(c[3])
        : "r"(a[0]), "r"(a[1]), "r"(a[2]), "r"(a[3]), "r"(b0), "r"(b1));
}
template<int NF>
__device__ __forceinline__ void zacc(float a[2][NF][4]) {
#pragma unroll
    for (int i = 0; i < 2; ++i)
#pragma unroll
        for (int j = 0; j < NF; ++j)
#pragma unroll
            for (int k = 0; k < 4; ++k) a[i][j][k] = 0.f;
}

// ---- GEMM: C[64x128] (+)= A[64x128] * W, A act tile, W weight tile [k][n] via ldsm.trans ----
__device__ __forceinline__ void gemm_w8(float acc[2][4][4], uint32_t At, uint32_t Wt,
                                        int w, int lane) {
    const int arow = (w & 1) * 32 + ((lane >> 3) & 1) * 8 + (lane & 7);
    const uint32_t abase = At + (uint32_t)arow * 256u;
    const uint32_t ax = (uint32_t)(arow & 7);
    const uint32_t atc = (uint32_t)((lane >> 4) & 1);
    const int kro = ((lane >> 4) & 1) * 8 + (lane & 7);
    const uint32_t kx = (uint32_t)(lane & 7);
    const uint32_t nch = 4u * (uint32_t)(w >> 1) + (uint32_t)((lane >> 3) & 1);
    const uint32_t bbase = Wt + (uint32_t)kro * 256u;
    const uint32_t bo0 = ((nch ^ kx) << 4), bo1 = (((nch + 2u) ^ kx) << 4);
#pragma unroll
    for (int s = 0; s < 8; ++s) {
        uint32_t ao = (((2u * (uint32_t)s + atc) ^ ax) << 4);
        uint32_t a0[4], a1[4], p[4], q[4];
        ldsm4(a0, abase + ao);
        ldsm4(a1, abase + 4096u + ao);
        ldsm4t(p, bbase + (uint32_t)s * 4096u + bo0);
        ldsm4t(q, bbase + (uint32_t)s * 4096u + bo1);
        mma16(acc[0][0], a0, p[0], p[2]); mma16(acc[1][0], a1, p[0], p[2]);
        mma16(acc[0][1], a0, p[1], p[3]); mma16(acc[1][1], a1, p[1], p[3]);
        mma16(acc[0][2], a0, q[0], q[2]); mma16(acc[1][2], a1, q[0], q[2]);
        mma16(acc[0][3], a0, q[1], q[3]); mma16(acc[1][3], a1, q[1], q[3]);
    }
}

// ---- fused dual GEMM (K and Q projections share A) ----
__device__ __forceinline__ void gemm_kq(float aK[2][4][4], float aQ[2][4][4],
                                        uint32_t At, uint32_t B0, uint32_t B1,
                                        int w, int lane) {
    const int arow = (w & 1) * 32 + ((lane >> 3) & 1) * 8 + (lane & 7);
    const uint32_t abase = At + (uint32_t)arow * 256u;
    const uint32_t ax = (uint32_t)(arow & 7);
    const uint32_t atc = (uint32_t)((lane >> 4) & 1);
    const int kro = ((lane >> 4) & 1) * 8 + (lane & 7);
    const uint32_t kx = (uint32_t)(lane & 7);
    const uint32_t nch = 4u * (uint32_t)(w >> 1) + (uint32_t)((lane >> 3) & 1);
    const uint32_t bb0 = B0 + (uint32_t)kro * 256u;
    const uint32_t bb1 = B1 + (uint32_t)kro * 256u;
    const uint32_t bo0 = ((nch ^ kx) << 4), bo1 = (((nch + 2u) ^ kx) << 4);
#pragma unroll
    for (int s = 0; s < 8; ++s) {
        uint32_t ao = (((2u * (uint32_t)s + atc) ^ ax) << 4);
        uint32_t a0[4], a1[4], p[4], q[4], r[4], t[4];
        ldsm4(a0, abase + ao);
        ldsm4(a1, abase + 4096u + ao);
        ldsm4t(p, bb0 + (uint32_t)s * 4096u + bo0);
        ldsm4t(q, bb0 + (uint32_t)s * 4096u + bo1);
        ldsm4t(r, bb1 + (uint32_t)s * 4096u + bo0);
        ldsm4t(t, bb1 + (uint32_t)s * 4096u + bo1);
        mma16(aK[0][0], a0, p[0], p[2]); mma16(aK[1][0], a1, p[0], p[2]);
        mma16(aK[0][1], a0, p[1], p[3]); mma16(aK[1][1], a1, p[1], p[3]);
        mma16(aK[0][2], a0, q[0], q[2]); mma16(aK[1][2], a1, q[0], q[2]);
        mma16(aK[0][3], a0, q[1], q[3]); mma16(aK[1][3], a1, q[1], q[3]);
        mma16(aQ[0][0], a0, r[0], r[2]); mma16(aQ[1][0], a1, r[0], r[2]);
        mma16(aQ[0][1], a0, r[1], r[3]); mma16(aQ[1][1], a1, r[1], r[3]);
        mma16(aQ[0][2], a0, t[0], t[2]); mma16(aQ[1][2], a1, t[0], t[2]);
        mma16(aQ[0][3], a0, t[1], t[3]); mma16(aQ[1][3], a1, t[1], t[3]);
    }
}

// ---- epilogue: fp32 acc -> f16 act tile ----
__device__ __forceinline__ void epi4(uint32_t dst, float acc[2][4][4], const float* bias,
                                     bool relu, int w, int lane) {
    const int r0 = (w & 1) * 32 + (lane >> 2);
    const int c0 = (w >> 1) * 32 + 2 * (lane & 3);
#pragma unroll
    for (int nf = 0; nf < 4; ++nf) {
        int col = c0 + 8 * nf;
        float b0 = bias ? __ldg(bias + col)     : 0.f;
        float b1 = bias ? __ldg(bias + col + 1) : 0.f;
#pragma unroll
        for (int mi = 0; mi < 2; ++mi)
#pragma unroll
            for (int hh = 0; hh < 2; ++hh) {
                int r = r0 + 16 * mi + 8 * hh;
                float v0 = acc[mi][nf][2 * hh + 0] + b0;
                float v1 = acc[mi][nf][2 * hh + 1] + b1;
                if (relu) { v0 = fmaxf(v0, 0.f); v1 = fmaxf(v1, 0.f); }
                sts32(dst + AS(r, col), pack2(v0, v1));
            }
    }
}

// ---- weight loader: gmem f32 [128][128] -> smem f16 [k][n] ----
__device__ __forceinline__ void wload(uint32_t dst, const float* Wg, int w, int lane) {
#pragma unroll
    for (int i = 0; i < 16; ++i) {
        int k = 16 * w + i;
        float4 v = __ldg(reinterpret_cast<const float4*>(Wg + (size_t)k * 128) + lane);
        int n = 4 * lane;
        uint32_t addr = dst + (uint32_t)k * 256u + ((((uint32_t)(n >> 3)) ^ (uint32_t)(k & 7)) << 4)
                        + (uint32_t)((n >> 2) & 1) * 8u;
        sts64(addr, pack2(v.x, v.y), pack2(v.z, v.w));
    }
}
// head weight f32 [128][32] -> f16 [k][n<32]
__device__ __forceinline__ void wload_head(uint32_t dst, const float* Wg, int w, int lane) {
#pragma unroll
    for (int it = 0; it < 4; ++it) {
        int k = 16 * w + 4 * it + (lane >> 3);
        int n = 4 * (lane & 7);
        float4 v = __ldg(reinterpret_cast<const float4*>(Wg + (size_t)k * 32) + (lane & 7));
        uint32_t addr = dst + (uint32_t)k * 256u + ((((uint32_t)(n >> 3)) ^ (uint32_t)(k & 7)) << 4)
                        + (uint32_t)((n >> 2) & 1) * 8u;
        sts64(addr, pack2(v.x, v.y), pack2(v.z, v.w));
    }
}

// ---- scores (diag) + in-register softmax + P->T2 (warps 0..3 only) ----
__device__ __forceinline__ void scores_softmax(uint32_t Qt, uint32_t Kt,
                                               const float* mask, int b0, int w, int lane) {
    const int g = w >> 1;
    const int gid = lane >> 2, ctig = lane & 3;
    const int arow = 16 * w + ((lane >> 3) & 1) * 8 + (lane & 7);
    const uint32_t abase = Qt + (uint32_t)arow * 256u;
    const uint32_t x7 = (uint32_t)(lane & 7);
    const uint32_t atc = (uint32_t)((lane >> 4) & 1);
    const int brow = 32 * g + ((lane >> 3) & 1) * 8 + (lane & 7);
    const uint32_t bb0 = Kt + (uint32_t)brow * 256u;
    const uint32_t bb1 = bb0 + 4096u;
    float aS[4][4];
#pragma unroll
    for (int j = 0; j < 4; ++j)
#pragma unroll
        for (int k = 0; k < 4; ++k) aS[j][k] = 0.f;
#pragma unroll
    for (int s = 0; s < 8; ++s) {
        uint32_t ao = (((2u * (uint32_t)s + atc) ^ x7) << 4);
        uint32_t qa[4], k0[4], k1[4];
        ldsm4(qa, abase + ao);
        ldsm4(k0, bb0 + ao);
        ldsm4(k1, bb1 + ao);
        mma16(aS[0], qa, k0[0], k0[2]);
        mma16(aS[1], qa, k0[1], k0[3]);
        mma16(aS[2], qa, k1[0], k1[2]);
        mma16(aS[3], qa, k1[1], k1[3]);
    }
    // rows iA = 16w+gid, iB = iA+8; batch-local il = 16*(w&1)+gid
    const float* mA = mask + (((size_t)(b0 + g)) * 32 + (16 * (w & 1) + gid)) * 32;
    const float* mB = mA + 8 * 32;
    float lA[8], lB[8];
#pragma unroll
    for (int nf = 0; nf < 4; ++nf)
#pragma unroll
        for (int e = 0; e < 2; ++e) {
            int cl = 8 * nf + 2 * ctig + e;
            float ma = __ldg(mA + cl), mb = __ldg(mB + cl);
            lA[2 * nf + e] = aS[nf][e]     * ma - 9e15f * (1.0f - ma);
            lB[2 * nf + e] = aS[nf][2 + e] * mb - 9e15f * (1.0f - mb);
        }
    float mxA = lA[0], mxB = lB[0];
#pragma unroll
    for (int j = 1; j < 8; ++j) { mxA = fmaxf(mxA, lA[j]); mxB = fmaxf(mxB, lB[j]); }
    mxA = fmaxf(mxA, __shfl_xor_sync(0xffffffffu, mxA, 1));
    mxA = fmaxf(mxA, __shfl_xor_sync(0xffffffffu, mxA, 2));
    mxB = fmaxf(mxB, __shfl_xor_sync(0xffffffffu, mxB, 1));
    mxB = fmaxf(mxB, __shfl_xor_sync(0xffffffffu, mxB, 2));
    float sA = 0.f, sB = 0.f;
#pragma unroll
    for (int j = 0; j < 8; ++j) {
        lA[j] = __expf(lA[j] - mxA); sA += lA[j];
        lB[j] = __expf(lB[j] - mxB); sB += lB[j];
    }
    sA += __shfl_xor_sync(0xffffffffu, sA, 1);
    sA += __shfl_xor_sync(0xffffffffu, sA, 2);
    sB += __shfl_xor_sync(0xffffffffu, sB, 1);
    sB += __shfl_xor_sync(0xffffffffu, sB, 2);
    float iA = 1.0f / sA, iB = 1.0f / sB;
    const int rA = 16 * w + gid;
#pragma unroll
    for (int nf = 0; nf < 4; ++nf) {
        int col = 32 * g + 8 * nf + 2 * ctig;
        sts32(Qt + AS(rA,     col), pack2(lA[2 * nf] * iA, lA[2 * nf + 1] * iA));
        sts32(Qt + AS(rA + 8, col), pack2(lB[2 * nf] * iB, lB[2 * nf + 1] * iB));
    }
}

// ---- PV (diag, K=32): A = P (T2), B = V (H) via trans ----
__device__ __forceinline__ void gemm_pv(float acc[2][4][4], uint32_t Pt, uint32_t Vt,
                                        int w, int lane) {
    const int b = w & 1;
    const int arow = 32 * b + ((lane >> 3) & 1) * 8 + (lane & 7);
    const uint32_t abase = Pt + (uint32_t)arow * 256u;
    const uint32_t ax = (uint32_t)(arow & 7);
    const uint32_t atc = (uint32_t)((lane >> 4) & 1);
    const int kro = ((lane >> 4) & 1) * 8 + (lane & 7);
    const uint32_t kx = (uint32_t)(lane & 7);
    const uint32_t nch = 4u * (uint32_t)(w >> 1) + (uint32_t)((lane >> 3) & 1);
    const uint32_t bbase = Vt + (uint32_t)(32 * b + kro) * 256u;
    const uint32_t bo0 = ((nch ^ kx) << 4), bo1 = (((nch + 2u) ^ kx) << 4);
#pragma unroll
    for (int s = 0; s < 2; ++s) {
        uint32_t ach = 4u * (uint32_t)b + 2u * (uint32_t)s + atc;
        uint32_t ao = ((ach ^ ax) << 4);
        uint32_t a0[4], a1[4], p[4], q[4];
        ldsm4(a0, abase + ao);
        ldsm4(a1, abase + 4096u + ao);
        ldsm4t(p, bbase + (uint32_t)s * 4096u + bo0);
        ldsm4t(q, bbase + (uint32_t)s * 4096u + bo1);
        mma16(acc[0][0], a0, p[0], p[2]); mma16(acc[1][0], a1, p[0], p[2]);
        mma16(acc[0][1], a0, p[1], p[3]); mma16(acc[1][1], a1, p[1], p[3]);
        mma16(acc[0][2], a0, q[0], q[2]); mma16(acc[1][2], a1, q[0], q[2]);
        mma16(acc[0][3], a0, q[1], q[3]); mma16(acc[1][3], a1, q[1], q[3]);
    }
}

template<bool LAST>
__device__ __forceinline__ void att_block(
    uint32_t H, uint32_t T1, uint32_t T2, uint32_t W0, uint32_t W1,
    const float* kb, const float* qb, const float* vw, const float* vb,
    const float* ow, const float* ob, const float* nw1, const float* nw2,
    const float* mask, int b0, int w, int lane)
{
    {   // K, Q projections (fused)
        float aK[2][4][4], aQ[2][4][4];
        zacc<4>(aK); zacc<4>(aQ);
        gemm_kq(aK, aQ, H, W0, W1, w, lane);
        __syncthreads();
        epi4(T1, aK, kb, true, w, lane);   // K -> T1 [j][h]
        epi4(T2, aQ, qb, true, w, lane);   // Q -> T2 [i][h]
        wload(W0, vw, w, lane);
        wload(W1, ow, w, lane);
        __syncthreads();
    }
    {   // V projection; then scores+softmax (warps 0-3), P overwrites own Q rows in T2
        float aV[2][4][4];
        zacc<4>(aV);
        gemm_w8(aV, H, W0, w, lane);
        __syncthreads();
        epi4(H, aV, vb, true, w, lane);    // V -> H [j][h]
        if (w < 4) scores_softmax(T2, T1, mask, b0, w, lane);
        if (LAST) wload_head(W0, nw1, w, lane); else wload(W0, nw1, w, lane);
        __syncthreads();
    }
    {   // PV (diag) -> T1
        float aP[2][4][4];
        zacc<4>(aP);
        gemm_pv(aP, T2, H, w, lane);
        __syncthreads();
        epi4(T1, aP, nullptr, false, w, lane);
        __syncthreads();
    }
    {   // out projection -> H
        float aO[2][4][4];
        zacc<4>(aO);
        gemm_w8(aO, T1, W1, w, lane);
        __syncthreads();
        epi4(H, aO, ob, true, w, lane);
        if (!LAST) wload(W1, nw2, w, lane);
        __syncthreads();
    }
}

__global__ void __launch_bounds__(256, 2)
dgn_f16(const float* __restrict__ x, const float* __restrict__ mask,
        const float* __restrict__ enc_w, const float* __restrict__ enc_b,
        const float* __restrict__ a1_vw, const float* __restrict__ a1_vb,
        const float* __restrict__ a1_kw, const float* __restrict__ a1_kb,
        const float* __restrict__ a1_qw, const float* __restrict__ a1_qb,
        const float* __restrict__ a1_ow, const float* __restrict__ a1_ob,
        const float* __restrict__ a2_vw, const float* __restrict__ a2_vb,
        const float* __restrict__ a2_kw, const float* __restrict__ a2_kb,
        const float* __restrict__ a2_qw, const float* __restrict__ a2_qb,
        const float* __restrict__ a2_ow, const float* __restrict__ a2_ob,
        const float* __restrict__ qhw, const float* __restrict__ qhb,
        float* __restrict__ out)
{
    extern __shared__ __align__(16) char sm[];
    const uint32_t base = s2u(sm);
    const uint32_t W0 = base + W0OFF, W1 = base + W1OFF;
    const uint32_t H = base + HOFF, T1 = base + T1OFF, T2 = base + T2OFF;
    const int tid = threadIdx.x, w = tid >> 5, lane = tid & 31;
    const int b0 = blockIdx.x * 2;

    // x (f32 [64][256]) -> f16 tiles T1 (cols 0-127), T2 (cols 128-255)
#pragma unroll
    for (int it = 0; it < 16; ++it) {
        int idx = tid + 256 * it;
        int r = idx >> 6, c4 = idx & 63;
        int col = 4 * c4;
        float4 v = *reinterpret_cast<const float4*>(
            x + (((size_t)b0 + (r >> 5)) * 32 + (r & 31)) * 256 + col);
        uint32_t dst = (col < 128 ? T1 : T2) + AS(r, col & 127);
        sts64(dst, pack2(v.x, v.y), pack2(v.z, v.w));
    }
    wload(W0, enc_w, w, lane);
    wload(W1, enc_w + 128 * 128, w, lane);
    __syncthreads();

    // encoder (K=256): two accumulating passes
    {
        float aE[2][4][4];
        zacc<4>(aE);
        gemm_w8(aE, T1, W0, w, lane);
        gemm_w8(aE, T2, W1, w, lane);
        __syncthreads();
        epi4(H, aE, enc_b, true, w, lane);
        wload(W0, a1_kw, w, lane);
        wload(W1, a1_qw, w, lane);
        __syncthreads();
    }

    att_block<false>(H, T1, T2, W0, W1,
                     a1_kb, a1_qb, a1_vw, a1_vb, a1_ow, a1_ob,
                     a2_kw, a2_qw, mask, b0, w, lane);
    att_block<true>(H, T1, T2, W0, W1,
                    a2_kb, a2_qb, a2_vw, a2_vb, a2_ow, a2_ob,
                    qhw, nullptr, mask, b0, w, lane);

    // head: N=32, 8 warps x n8; B = W0 (qhw) via ldsm x2 trans
    {
        const int arow = (w & 1) * 32 + ((lane >> 3) & 1) * 8 + (lane & 7);
        const uint32_t abase = H + (uint32_t)arow * 256u;
        const uint32_t ax = (uint32_t)(arow & 7);
        const uint32_t atc = (uint32_t)((lane >> 4) & 1);
        const int kro2 = ((lane >> 3) & 1) * 8 + (lane & 7);
        const uint32_t bb = W0 + (uint32_t)kro2 * 256u;
        const uint32_t boH = (((uint32_t)(w >> 1) ^ (uint32_t)(lane & 7)) << 4);
        float acc[2][4];
#pragma unroll
        for (int i = 0; i < 2; ++i)
#pragma unroll
            for (int k = 0; k < 4; ++k) acc[i][k] = 0.f;
#pragma unroll
        for (int s = 0; s < 8; ++s) {
            uint32_t ao = (((2u * (uint32_t)s + atc) ^ ax) << 4);
            uint32_t a0[4], a1[4], b[2];
            ldsm4(a0, abase + ao);
            ldsm4(a1, abase + 4096u + ao);
            ldsm2t(b, bb + (uint32_t)s * 4096u + boH);
            mma16(acc[0], a0, b[0], b[1]);
            mma16(acc[1], a1, b[0], b[1]);
        }
        const int r0 = (w & 1) * 32 + (lane >> 2);
        const int col = (w >> 1) * 8 + 2 * (lane & 3);
        float bb0 = __ldg(qhb + col), bb1 = __ldg(qhb + col + 1);
#pragma unroll
        for (int mi = 0; mi < 2; ++mi)
#pragma unroll
            for (int hh = 0; hh < 2; ++hh) {
                int r = r0 + 16 * mi + 8 * hh;
                float2 v = make_float2(acc[mi][2 * hh] + bb0, acc[mi][2 * hh + 1] + bb1);
                *reinterpret_cast<float2*>(
                    out + (((size_t)b0 + (r >> 5)) * 32 + (r & 31)) * 32 + col) = v;
            }
    }
}

extern "C" void kernel_launch(void* const* d_in, const int* in_sizes, int n_in,
                              void* d_out, int out_size)
{
    cudaFuncSetAttribute(dgn_f16, cudaFuncAttributeMaxDynamicSharedMemorySize, SM_TOTAL);
    dgn_f16<<<2048, 256, SM_TOTAL>>>(
        (const float*)d_in[0],  (const float*)d_in[1],  (const float*)d_in[2],  (const float*)d_in[3],
        (const float*)d_in[4],  (const float*)d_in[5],  (const float*)d_in[6],  (const float*)d_in[7],
        (const float*)d_in[8],  (const float*)d_in[9],  (const float*)d_in[10], (const float*)d_in[11],
        (const float*)d_in[12], (const float*)d_in[13], (const float*)d_in[14], (const float*)d_in[15],
        (const float*)d_in[16], (const float*)d_in[17], (const float*)d_in[18], (const float*)d_in[19],
        (const float*)d_in[20], (const float*)d_in[21], (float*)d_out);
}

// round 9
// speedup vs baseline: 7.4058x; 1.2711x over previous
#include <cuda_runtime.h>
#include <cuda_fp16.h>
#include <cstdint>

// smem (bytes): W0,W1 = 32KB f16 weight tiles [k=128][n=128]; H,T1,T2 = 16KB f16 act tiles [64][128]
#define W0OFF 0
#define W1OFF 32768
#define HOFF  65536
#define T1OFF 81920
#define T2OFF 98304
#define SM_TOTAL 114688   // 112KB -> 2 CTAs/SM

// pre-swizzled f16 weight tile images (exact smem layout), built once per launch
__device__ __align__(16) unsigned char g_wtiles[11][32768];

// f16 tile swizzle: [row][col] (128 cols), row stride 256B, 16B-chunk XOR
__device__ __forceinline__ uint32_t AS(int r, int c) {
    return (uint32_t)(r * 256 + (((c >> 3) ^ (r & 7)) << 4) + (c & 7) * 2);
}
__device__ __forceinline__ uint32_t s2u(const void* p) {
    uint32_t a;
    asm("{ .reg .u64 t; cvta.to.shared.u64 t, %1; cvt.u32.u64 %0, t; }" : "=r"(a) : "l"(p));
    return a;
}
__device__ __forceinline__ uint32_t pack2(float a, float b) {
    __half2 h = __floats2half2_rn(a, b);
    return *reinterpret_cast<uint32_t*>(&h);
}
__device__ __forceinline__ void sts32(uint32_t a, uint32_t v) {
    asm volatile("st.shared.b32 [%0], %1;" :: "r"(a), "r"(v));
}
__device__ __forceinline__ void sts64(uint32_t a, uint32_t x, uint32_t y) {
    asm volatile("st.shared.v2.b32 [%0], {%1,%2};" :: "r"(a), "r"(x), "r"(y));
}
__device__ __forceinline__ void ldsm4(uint32_t r[4], uint32_t a) {
    asm volatile("ldmatrix.sync.aligned.m8n8.x4.shared.b16 {%0,%1,%2,%3}, [%4];"
        : "=r"(r[0]), "=r"(r[1]), "=r"(r[2]), "=r"(r[3]) : "r"(a));
}
__device__ __forceinline__ void ldsm4t(uint32_t r[4], uint32_t a) {
    asm volatile("ldmatrix.sync.aligned.m8n8.x4.trans.shared.b16 {%0,%1,%2,%3}, [%4];"
        : "=r"(r[0]), "=r"(r[1]), "=r"(r[2]), "=r"(r[3]) : "r"(a));
}
__device__ __forceinline__ void ldsm2t(uint32_t r[2], uint32_t a) {
    asm volatile("ldmatrix.sync.aligned.m8n8.x2.trans.shared.b16 {%0,%1}, [%2];"
        : "=r"(r[0]), "=r"(r[1]) : "r"(a));
}
__device__ __forceinline__ void mma16(float c[4], const uint32_t a[4], uint32_t b0, uint32_t b1) {
    asm volatile("mma.sync.aligned.m16n8k16.row.col.f32.f16.f16.f32 "
        "{%0,%1,%2,%3}, {%4,%5,%6,%7}, {%8,%9}, {%0,%1,%2,%3};"
        : "+f"(c[0]), "+f"(c[1]), "+f"(c[2]), "+f"(c[3])
        : "r"(a[0]), "r"(a[1]), "r"(a[2]), "r"(a[3]), "r"(b0), "r"(b1));
}
template<int NF>
__device__ __forceinline__ void zacc(float a[2][NF][4]) {
#pragma unroll
    for (int i = 0; i < 2; ++i)
#pragma unroll
        for (int j = 0; j < NF; ++j)
#pragma unroll
            for (int k = 0; k < 4; ++k) a[i][j][k] = 0.f;
}

// ---- async weight tile copy: linear 32KB, 8 x 16B per thread ----
__device__ __forceinline__ void wcopy(uint32_t dstS, int m, int tid) {
#pragma unroll
    for (int i = 0; i < 8; ++i) {
        uint32_t off = (uint32_t)(tid + 256 * i) * 16u;
        asm volatile("{ .reg .u64 gp; cvta.to.global.u64 gp, %1;\n\t"
                     "cp.async.cg.shared.global [%0], [gp], 16; }"
                     :: "r"(dstS + off), "l"(g_wtiles[m] + off));
    }
}
#define CP_WAIT() asm volatile("cp.async.wait_all;" ::: "memory")

// ---- GEMM: C[64x128] (+)= A[64x128] * W, A act tile, W weight tile [k][n] via ldsm.trans ----
__device__ __forceinline__ void gemm_w8(float acc[2][4][4], uint32_t At, uint32_t Wt,
                                        int w, int lane) {
    const int arow = (w & 1) * 32 + ((lane >> 3) & 1) * 8 + (lane & 7);
    const uint32_t abase = At + (uint32_t)arow * 256u;
    const uint32_t ax = (uint32_t)(arow & 7);
    const uint32_t atc = (uint32_t)((lane >> 4) & 1);
    const int kro = ((lane >> 4) & 1) * 8 + (lane & 7);
    const uint32_t kx = (uint32_t)(lane & 7);
    const uint32_t nch = 4u * (uint32_t)(w >> 1) + (uint32_t)((lane >> 3) & 1);
    const uint32_t bbase = Wt + (uint32_t)kro * 256u;
    const uint32_t bo0 = ((nch ^ kx) << 4), bo1 = (((nch + 2u) ^ kx) << 4);
#pragma unroll
    for (int s = 0; s < 8; ++s) {
        uint32_t ao = (((2u * (uint32_t)s + atc) ^ ax) << 4);
        uint32_t a0[4], a1[4], p[4], q[4];
        ldsm4(a0, abase + ao);
        ldsm4(a1, abase + 4096u + ao);
        ldsm4t(p, bbase + (uint32_t)s * 4096u + bo0);
        ldsm4t(q, bbase + (uint32_t)s * 4096u + bo1);
        mma16(acc[0][0], a0, p[0], p[2]); mma16(acc[1][0], a1, p[0], p[2]);
        mma16(acc[0][1], a0, p[1], p[3]); mma16(acc[1][1], a1, p[1], p[3]);
        mma16(acc[0][2], a0, q[0], q[2]); mma16(acc[1][2], a1, q[0], q[2]);
        mma16(acc[0][3], a0, q[1], q[3]); mma16(acc[1][3], a1, q[1], q[3]);
    }
}

// ---- fused dual GEMM (K and Q projections share A) ----
__device__ __forceinline__ void gemm_kq(float aK[2][4][4], float aQ[2][4][4],
                                        uint32_t At, uint32_t B0, uint32_t B1,
                                        int w, int lane) {
    const int arow = (w & 1) * 32 + ((lane >> 3) & 1) * 8 + (lane & 7);
    const uint32_t abase = At + (uint32_t)arow * 256u;
    const uint32_t ax = (uint32_t)(arow & 7);
    const uint32_t atc = (uint32_t)((lane >> 4) & 1);
    const int kro = ((lane >> 4) & 1) * 8 + (lane & 7);
    const uint32_t kx = (uint32_t)(lane & 7);
    const uint32_t nch = 4u * (uint32_t)(w >> 1) + (uint32_t)((lane >> 3) & 1);
    const uint32_t bb0 = B0 + (uint32_t)kro * 256u;
    const uint32_t bb1 = B1 + (uint32_t)kro * 256u;
    const uint32_t bo0 = ((nch ^ kx) << 4), bo1 = (((nch + 2u) ^ kx) << 4);
#pragma unroll
    for (int s = 0; s < 8; ++s) {
        uint32_t ao = (((2u * (uint32_t)s + atc) ^ ax) << 4);
        uint32_t a0[4], a1[4], p[4], q[4], r[4], t[4];
        ldsm4(a0, abase + ao);
        ldsm4(a1, abase + 4096u + ao);
        ldsm4t(p, bb0 + (uint32_t)s * 4096u + bo0);
        ldsm4t(q, bb0 + (uint32_t)s * 4096u + bo1);
        ldsm4t(r, bb1 + (uint32_t)s * 4096u + bo0);
        ldsm4t(t, bb1 + (uint32_t)s * 4096u + bo1);
        mma16(aK[0][0], a0, p[0], p[2]); mma16(aK[1][0], a1, p[0], p[2]);
        mma16(aK[0][1], a0, p[1], p[3]); mma16(aK[1][1], a1, p[1], p[3]);
        mma16(aK[0][2], a0, q[0], q[2]); mma16(aK[1][2], a1, q[0], q[2]);
        mma16(aK[0][3], a0, q[1], q[3]); mma16(aK[1][3], a1, q[1], q[3]);
        mma16(aQ[0][0], a0, r[0], r[2]); mma16(aQ[1][0], a1, r[0], r[2]);
        mma16(aQ[0][1], a0, r[1], r[3]); mma16(aQ[1][1], a1, r[1], r[3]);
        mma16(aQ[0][2], a0, t[0], t[2]); mma16(aQ[1][2], a1, t[0], t[2]);
        mma16(aQ[0][3], a0, t[1], t[3]); mma16(aQ[1][3], a1, t[1], t[3]);
    }
}

// ---- epilogue: fp32 acc -> f16 act tile ----
__device__ __forceinline__ void epi4(uint32_t dst, float acc[2][4][4], const float* bias,
                                     bool relu, int w, int lane) {
    const int r0 = (w & 1) * 32 + (lane >> 2);
    const int c0 = (w >> 1) * 32 + 2 * (lane & 3);
#pragma unroll
    for (int nf = 0; nf < 4; ++nf) {
        int col = c0 + 8 * nf;
        float b0 = bias ? __ldg(bias + col)     : 0.f;
        float b1 = bias ? __ldg(bias + col + 1) : 0.f;
#pragma unroll
        for (int mi = 0; mi < 2; ++mi)
#pragma unroll
            for (int hh = 0; hh < 2; ++hh) {
                int r = r0 + 16 * mi + 8 * hh;
                float v0 = acc[mi][nf][2 * hh + 0] + b0;
                float v1 = acc[mi][nf][2 * hh + 1] + b1;
                if (relu) { v0 = fmaxf(v0, 0.f); v1 = fmaxf(v1, 0.f); }
                sts32(dst + AS(r, col), pack2(v0, v1));
            }
    }
}

// ---- scores (diag) + in-register softmax + P->T2 (warps 0..3 only) ----
__device__ __forceinline__ void scores_softmax(uint32_t Qt, uint32_t Kt,
                                               const float* mask, int b0, int w, int lane) {
    const int g = w >> 1;
    const int gid = lane >> 2, ctig = lane & 3;
    const int arow = 16 * w + ((lane >> 3) & 1) * 8 + (lane & 7);
    const uint32_t abase = Qt + (uint32_t)arow * 256u;
    const uint32_t x7 = (uint32_t)(lane & 7);
    const uint32_t atc = (uint32_t)((lane >> 4) & 1);
    const int brow = 32 * g + ((lane >> 3) & 1) * 8 + (lane & 7);
    const uint32_t bb0 = Kt + (uint32_t)brow * 256u;
    const uint32_t bb1 = bb0 + 4096u;
    float aS[4][4];
#pragma unroll
    for (int j = 0; j < 4; ++j)
#pragma unroll
        for (int k = 0; k < 4; ++k) aS[j][k] = 0.f;
#pragma unroll
    for (int s = 0; s < 8; ++s) {
        uint32_t ao = (((2u * (uint32_t)s + atc) ^ x7) << 4);
        uint32_t qa[4], k0[4], k1[4];
        ldsm4(qa, abase + ao);
        ldsm4(k0, bb0 + ao);
        ldsm4(k1, bb1 + ao);
        mma16(aS[0], qa, k0[0], k0[2]);
        mma16(aS[1], qa, k0[1], k0[3]);
        mma16(aS[2], qa, k1[0], k1[2]);
        mma16(aS[3], qa, k1[1], k1[3]);
    }
    const float* mA = mask + (((size_t)(b0 + g)) * 32 + (16 * (w & 1) + gid)) * 32;
    const float* mB = mA + 8 * 32;
    float lA[8], lB[8];
#pragma unroll
    for (int nf = 0; nf < 4; ++nf)
#pragma unroll
        for (int e = 0; e < 2; ++e) {
            int cl = 8 * nf + 2 * ctig + e;
            float ma = __ldg(mA + cl), mb = __ldg(mB + cl);
            lA[2 * nf + e] = aS[nf][e]     * ma - 9e15f * (1.0f - ma);
            lB[2 * nf + e] = aS[nf][2 + e] * mb - 9e15f * (1.0f - mb);
        }
    float mxA = lA[0], mxB = lB[0];
#pragma unroll
    for (int j = 1; j < 8; ++j) { mxA = fmaxf(mxA, lA[j]); mxB = fmaxf(mxB, lB[j]); }
    mxA = fmaxf(mxA, __shfl_xor_sync(0xffffffffu, mxA, 1));
    mxA = fmaxf(mxA, __shfl_xor_sync(0xffffffffu, mxA, 2));
    mxB = fmaxf(mxB, __shfl_xor_sync(0xffffffffu, mxB, 1));
    mxB = fmaxf(mxB, __shfl_xor_sync(0xffffffffu, mxB, 2));
    float sA = 0.f, sB = 0.f;
#pragma unroll
    for (int j = 0; j < 8; ++j) {
        lA[j] = __expf(lA[j] - mxA); sA += lA[j];
        lB[j] = __expf(lB[j] - mxB); sB += lB[j];
    }
    sA += __shfl_xor_sync(0xffffffffu, sA, 1);
    sA += __shfl_xor_sync(0xffffffffu, sA, 2);
    sB += __shfl_xor_sync(0xffffffffu, sB, 1);
    sB += __shfl_xor_sync(0xffffffffu, sB, 2);
    float iA = 1.0f / sA, iB = 1.0f / sB;
    const int rA = 16 * w + gid;
#pragma unroll
    for (int nf = 0; nf < 4; ++nf) {
        int col = 32 * g + 8 * nf + 2 * ctig;
        sts32(Qt + AS(rA,     col), pack2(lA[2 * nf] * iA, lA[2 * nf + 1] * iA));
        sts32(Qt + AS(rA + 8, col), pack2(lB[2 * nf] * iB, lB[2 * nf + 1] * iB));
    }
}

// ---- PV (diag, K=32): A = P (T2), B = V (H) via trans ----
__device__ __forceinline__ void gemm_pv(float acc[2][4][4], uint32_t Pt, uint32_t Vt,
                                        int w, int lane) {
    const int b = w & 1;
    const int arow = 32 * b + ((lane >> 3) & 1) * 8 + (lane & 7);
    const uint32_t abase = Pt + (uint32_t)arow * 256u;
    const uint32_t ax = (uint32_t)(arow & 7);
    const uint32_t atc = (uint32_t)((lane >> 4) & 1);
    const int kro = ((lane >> 4) & 1) * 8 + (lane & 7);
    const uint32_t kx = (uint32_t)(lane & 7);
    const uint32_t nch = 4u * (uint32_t)(w >> 1) + (uint32_t)((lane >> 3) & 1);
    const uint32_t bbase = Vt + (uint32_t)(32 * b + kro) * 256u;
    const uint32_t bo0 = ((nch ^ kx) << 4), bo1 = (((nch + 2u) ^ kx) << 4);
#pragma unroll
    for (int s = 0; s < 2; ++s) {
        uint32_t ach = 4u * (uint32_t)b + 2u * (uint32_t)s + atc;
        uint32_t ao = ((ach ^ ax) << 4);
        uint32_t a0[4], a1[4], p[4], q[4];
        ldsm4(a0, abase + ao);
        ldsm4(a1, abase + 4096u + ao);
        ldsm4t(p, bbase + (uint32_t)s * 4096u + bo0);
        ldsm4t(q, bbase + (uint32_t)s * 4096u + bo1);
        mma16(acc[0][0], a0, p[0], p[2]); mma16(acc[1][0], a1, p[0], p[2]);
        mma16(acc[0][1], a0, p[1], p[3]); mma16(acc[1][1], a1, p[1], p[3]);
        mma16(acc[0][2], a0, q[0], q[2]); mma16(acc[1][2], a1, q[0], q[2]);
        mma16(acc[0][3], a0, q[1], q[3]); mma16(acc[1][3], a1, q[1], q[3]);
    }
}

__device__ __forceinline__ void att_block(
    uint32_t H, uint32_t T1, uint32_t T2, uint32_t W0, uint32_t W1,
    const float* kb, const float* qb, const float* vb, const float* ob,
    const float* mask, int b0, int mv, int mo, int mn1, int mn2,
    int w, int lane, int tid)
{
    {   // K, Q projections (fused)
        float aK[2][4][4], aQ[2][4][4];
        zacc<4>(aK); zacc<4>(aQ);
        gemm_kq(aK, aQ, H, W0, W1, w, lane);
        __syncthreads();
        wcopy(W0, mv, tid);
        wcopy(W1, mo, tid);
        epi4(T1, aK, kb, true, w, lane);   // K -> T1 [j][h]
        epi4(T2, aQ, qb, true, w, lane);   // Q -> T2 [i][h]
        CP_WAIT();
        __syncthreads();
    }
    {   // V projection; scores+softmax on warps 0-3 (P overwrites own Q rows in T2)
        float aV[2][4][4];
        zacc<4>(aV);
        gemm_w8(aV, H, W0, w, lane);
        __syncthreads();
        if (mn1 >= 0) wcopy(W0, mn1, tid);
        epi4(H, aV, vb, true, w, lane);    // V -> H [j][h]
        if (w < 4) scores_softmax(T2, T1, mask, b0, w, lane);
        CP_WAIT();
        __syncthreads();
    }
    {   // PV (diag) -> T1
        float aP[2][4][4];
        zacc<4>(aP);
        gemm_pv(aP, T2, H, w, lane);
        __syncthreads();
        epi4(T1, aP, nullptr, false, w, lane);
        __syncthreads();
    }
    {   // out projection -> H
        float aO[2][4][4];
        zacc<4>(aO);
        gemm_w8(aO, T1, W1, w, lane);
        __syncthreads();
        if (mn2 >= 0) wcopy(W1, mn2, tid);
        epi4(H, aO, ob, true, w, lane);
        CP_WAIT();
        __syncthreads();
    }
}

__global__ void __launch_bounds__(256, 2)
dgn_f16(const float* __restrict__ x, const float* __restrict__ mask,
        const float* __restrict__ enc_b,
        const float* __restrict__ a1_vb, const float* __restrict__ a1_kb,
        const float* __restrict__ a1_qb, const float* __restrict__ a1_ob,
        const float* __restrict__ a2_vb, const float* __restrict__ a2_kb,
        const float* __restrict__ a2_qb, const float* __restrict__ a2_ob,
        const float* __restrict__ qhb,
        float* __restrict__ out)
{
    extern __shared__ __align__(16) char sm[];
    const uint32_t base = s2u(sm);
    const uint32_t W0 = base + W0OFF, W1 = base + W1OFF;
    const uint32_t H = base + HOFF, T1 = base + T1OFF, T2 = base + T2OFF;
    const int tid = threadIdx.x, w = tid >> 5, lane = tid & 31;
    const int b0 = blockIdx.x * 2;

    wcopy(W0, 0, tid);
    wcopy(W1, 1, tid);
    // x (f32 [64][256]) -> f16 tiles T1 (cols 0-127), T2 (cols 128-255)
#pragma unroll
    for (int it = 0; it < 16; ++it) {
        int idx = tid + 256 * it;
        int r = idx >> 6, c4 = idx & 63;
        int col = 4 * c4;
        float4 v = *reinterpret_cast<const float4*>(
            x + (((size_t)b0 + (r >> 5)) * 32 + (r & 31)) * 256 + col);
        uint32_t dst = (col < 128 ? T1 : T2) + AS(r, col & 127);
        sts64(dst, pack2(v.x, v.y), pack2(v.z, v.w));
    }
    CP_WAIT();
    __syncthreads();

    // encoder (K=256): two accumulating passes
    {
        float aE[2][4][4];
        zacc<4>(aE);
        gemm_w8(aE, T1, W0, w, lane);
        gemm_w8(aE, T2, W1, w, lane);
        __syncthreads();
        wcopy(W0, 2, tid);
        wcopy(W1, 3, tid);
        epi4(H, aE, enc_b, true, w, lane);
        CP_WAIT();
        __syncthreads();
    }

    att_block(H, T1, T2, W0, W1, a1_kb, a1_qb, a1_vb, a1_ob,
              mask, b0, 4, 5, 6, 7, w, lane, tid);
    att_block(H, T1, T2, W0, W1, a2_kb, a2_qb, a2_vb, a2_ob,
              mask, b0, 8, 9, 10, -1, w, lane, tid);

    // head: N=32, 8 warps x n8; B = W0 (tile 10 = qhw) via ldsm x2 trans
    {
        const int arow = (w & 1) * 32 + ((lane >> 3) & 1) * 8 + (lane & 7);
        const uint32_t abase = H + (uint32_t)arow * 256u;
        const uint32_t ax = (uint32_t)(arow & 7);
        const uint32_t atc = (uint32_t)((lane >> 4) & 1);
        const int kro2 = ((lane >> 3) & 1) * 8 + (lane & 7);
        const uint32_t bb = W0 + (uint32_t)kro2 * 256u;
        const uint32_t boH = (((uint32_t)(w >> 1) ^ (uint32_t)(lane & 7)) << 4);
        float acc[2][4];
#pragma unroll
        for (int i = 0; i < 2; ++i)
#pragma unroll
            for (int k = 0; k < 4; ++k) acc[i][k] = 0.f;
#pragma unroll
        for (int s = 0; s < 8; ++s) {
            uint32_t ao = (((2u * (uint32_t)s + atc) ^ ax) << 4);
            uint32_t a0[4], a1[4], b[2];
            ldsm4(a0, abase + ao);
            ldsm4(a1, abase + 4096u + ao);
            ldsm2t(b, bb + (uint32_t)s * 4096u + boH);
            mma16(acc[0], a0, b[0], b[1]);
            mma16(acc[1], a1, b[0], b[1]);
        }
        const int r0 = (w & 1) * 32 + (lane >> 2);
        const int col = (w >> 1) * 8 + 2 * (lane & 3);
        float bb0 = __ldg(qhb + col), bb1 = __ldg(qhb + col + 1);
#pragma unroll
        for (int mi = 0; mi < 2; ++mi)
#pragma unroll
            for (int hh = 0; hh < 2; ++hh) {
                int r = r0 + 16 * mi + 8 * hh;
                float2 v = make_float2(acc[mi][2 * hh] + bb0, acc[mi][2 * hh + 1] + bb1);
                *reinterpret_cast<float2*>(
                    out + (((size_t)b0 + (r >> 5)) * 32 + (r & 31)) * 32 + col) = v;
            }
    }
}

// ---- prep: bake f32 weights into pre-swizzled f16 tile images ----
__global__ void wprep(const float* __restrict__ enc_w,
                      const float* __restrict__ k1, const float* __restrict__ q1,
                      const float* __restrict__ v1, const float* __restrict__ o1,
                      const float* __restrict__ k2, const float* __restrict__ q2,
                      const float* __restrict__ v2, const float* __restrict__ o2,
                      const float* __restrict__ hw)
{
    const int m = blockIdx.x, tid = threadIdx.x, w = tid >> 5, lane = tid & 31;
    unsigned char* dst = g_wtiles[m];
    const float* srcs[11] = { enc_w, enc_w + 128 * 128, k1, q1, v1, o1, k2, q2, v2, o2, hw };
    const float* src = srcs[m];
    if (m < 10) {
#pragma unroll
        for (int i = 0; i < 16; ++i) {
            int k = 16 * w + i;
            float4 v = __ldg(reinterpret_cast<const float4*>(src + (size_t)k * 128) + lane);
            int n = 4 * lane;
            uint32_t off = (uint32_t)k * 256u + ((((uint32_t)(n >> 3)) ^ (uint32_t)(k & 7)) << 4)
                           + (uint32_t)((n >> 2) & 1) * 8u;
            uint2 val = make_uint2(pack2(v.x, v.y), pack2(v.z, v.w));
            *reinterpret_cast<uint2*>(dst + off) = val;
        }
    } else {
        for (int i = tid; i < 2048; i += 256)
            reinterpret_cast<uint4*>(dst)[i] = make_uint4(0, 0, 0, 0);
        __syncthreads();
#pragma unroll
        for (int it = 0; it < 4; ++it) {
            int k = 16 * w + 4 * it + (lane >> 3);
            int n = 4 * (lane & 7);
            float4 v = __ldg(reinterpret_cast<const float4*>(src + (size_t)k * 32) + (lane & 7));
            uint32_t off = (uint32_t)k * 256u + ((((uint32_t)(n >> 3)) ^ (uint32_t)(k & 7)) << 4)
                           + (uint32_t)((n >> 2) & 1) * 8u;
            uint2 val = make_uint2(pack2(v.x, v.y), pack2(v.z, v.w));
            *reinterpret_cast<uint2*>(dst + off) = val;
        }
    }
}

extern "C" void kernel_launch(void* const* d_in, const int* in_sizes, int n_in,
                              void* d_out, int out_size)
{
    const float* x     = (const float*)d_in[0];
    const float* mask  = (const float*)d_in[1];
    const float* enc_w = (const float*)d_in[2];
    const float* enc_b = (const float*)d_in[3];
    const float* a1_vw = (const float*)d_in[4];
    const float* a1_vb = (const float*)d_in[5];
    const float* a1_kw = (const float*)d_in[6];
    const float* a1_kb = (const float*)d_in[7];
    const float* a1_qw = (const float*)d_in[8];
    const float* a1_qb = (const float*)d_in[9];
    const float* a1_ow = (const float*)d_in[10];
    const float* a1_ob = (const float*)d_in[11];
    const float* a2_vw = (const float*)d_in[12];
    const float* a2_vb = (const float*)d_in[13];
    const float* a2_kw = (const float*)d_in[14];
    const float* a2_kb = (const float*)d_in[15];
    const float* a2_qw = (const float*)d_in[16];
    const float* a2_qb = (const float*)d_in[17];
    const float* a2_ow = (const float*)d_in[18];
    const float* a2_ob = (const float*)d_in[19];
    const float* q_w   = (const float*)d_in[20];
    const float* q_b   = (const float*)d_in[21];

    wprep<<<11, 256>>>(enc_w, a1_kw, a1_qw, a1_vw, a1_ow,
                       a2_kw, a2_qw, a2_vw, a2_ow, q_w);

    cudaFuncSetAttribute(dgn_f16, cudaFuncAttributeMaxDynamicSharedMemorySize, SM_TOTAL);
    dgn_f16<<<2048, 256, SM_TOTAL>>>(
        x, mask, enc_b,
        a1_vb, a1_kb, a1_qb, a1_ob,
        a2_vb, a2_kb, a2_qb, a2_ob,
        q_b, (float*)d_out);
}